// round 1
// baseline (speedup 1.0000x reference)
#include <cuda_runtime.h>
#include <math.h>

#define T_SEQ 2048
#define D_EMB 2048
#define HD    128
#define NHEADS 16

// Scratch (no allocs allowed): Q,K,V,R in (t, n*h) concat layout, 16 MB each.
__device__ float g_Q[T_SEQ * D_EMB];
__device__ float g_K[T_SEQ * D_EMB];
__device__ float g_V[T_SEQ * D_EMB];
__device__ float g_R[T_SEQ * D_EMB];

// ---------------------------------------------------------------------------
// Tiled fp32 GEMM: C[M,N] = A[M,K] @ B
//   BMODE 0: B is plain row-major [K,N]
//   BMODE 1: B is per-head weights W[n, d, h] viewed as [K=d, N=n*h]:
//            B(k, c) = W[(c>>7)*D*H + k*H + (c&127)]
// Tile: BM=128, BN=64, BK=16, 256 threads, each thread 8x4 outputs.
// ---------------------------------------------------------------------------
template <int BMODE>
__global__ __launch_bounds__(256) void gemm128x64(const float* __restrict__ A,
                                                  const float* __restrict__ B,
                                                  float* __restrict__ C,
                                                  int M, int N, int K) {
    __shared__ float As[16][132];  // transposed A tile, +4 pad
    __shared__ float Bs[16][64];

    const int bm = blockIdx.y * 128;
    const int bn = blockIdx.x * 64;
    const int tid = threadIdx.x;
    const int tx = tid & 15;
    const int ty = tid >> 4;

    float acc[8][4];
#pragma unroll
    for (int i = 0; i < 8; i++)
#pragma unroll
        for (int j = 0; j < 4; j++) acc[i][j] = 0.0f;

    const int am = tid >> 1;       // A-tile row 0..127
    const int ae = (tid & 1) * 2;  // which pair of float4s along k
    const int bk = tid >> 4;       // B-tile k row 0..15
    const int bnq = tid & 15;      // B-tile float4 column index

    for (int k0 = 0; k0 < K; k0 += 16) {
        // Load A tile (128x16), store transposed into As[k][m]
#pragma unroll
        for (int e = 0; e < 2; e++) {
            const int kq = ae + e;
            const float4 av = *reinterpret_cast<const float4*>(
                &A[(size_t)(bm + am) * K + k0 + kq * 4]);
            As[kq * 4 + 0][am] = av.x;
            As[kq * 4 + 1][am] = av.y;
            As[kq * 4 + 2][am] = av.z;
            As[kq * 4 + 3][am] = av.w;
        }
        // Load B tile (16x64)
        float4 bv;
        if (BMODE == 0) {
            bv = *reinterpret_cast<const float4*>(
                &B[(size_t)(k0 + bk) * N + bn + bnq * 4]);
        } else {
            const int c = bn + bnq * 4;  // stays within one head (bn mult of 64)
            bv = *reinterpret_cast<const float4*>(
                &B[(size_t)(c >> 7) * (D_EMB * HD) + (size_t)(k0 + bk) * HD +
                   (c & 127)]);
        }
        *reinterpret_cast<float4*>(&Bs[bk][bnq * 4]) = bv;
        __syncthreads();

#pragma unroll
        for (int k = 0; k < 16; k++) {
            float a_[8], b_[4];
#pragma unroll
            for (int i = 0; i < 8; i++) a_[i] = As[k][ty * 8 + i];
#pragma unroll
            for (int j = 0; j < 4; j++) b_[j] = Bs[k][tx * 4 + j];
#pragma unroll
            for (int i = 0; i < 8; i++)
#pragma unroll
                for (int j = 0; j < 4; j++)
                    acc[i][j] = fmaf(a_[i], b_[j], acc[i][j]);
        }
        __syncthreads();
    }

#pragma unroll
    for (int i = 0; i < 8; i++) {
        float4 v = make_float4(acc[i][0], acc[i][1], acc[i][2], acc[i][3]);
        *reinterpret_cast<float4*>(
            &C[(size_t)(bm + ty * 8 + i) * N + bn + tx * 4]) = v;
    }
}

// ---------------------------------------------------------------------------
// Flash attention (fp32, online softmax).
// One block = (head n, 64 query rows). 256 threads, thread tile:
//   S phase: 4 (m) x 4 (s);  O phase: 4 (m) x 8 (h).
// ---------------------------------------------------------------------------
__global__ __launch_bounds__(256) void attn_kernel() {
    extern __shared__ float sm[];
    float* Qs = sm;                // [128][64]  Qs[h*64+m], pre-scaled
    float* Ks = Qs + HD * 64;      // [128][64]  Ks[h*64+s]
    float* Vs = Ks + HD * 64;      // [64][128]  Vs[s*128+h]
    float* Ps = Vs + 64 * HD;      // [64][68]   Ps[s*68+m] (pad 4)

    const int n = blockIdx.y;
    const int m0 = blockIdx.x * 64;
    const int tid = threadIdx.x;
    const int tx = tid & 15;
    const int ty = tid >> 4;
    const float scale = 0.08838834764831843f;  // 1/sqrt(128)

    const float* Qg = g_Q + (size_t)m0 * D_EMB + n * HD;
    for (int i = tid; i < 64 * HD; i += 256) {
        const int m = i >> 7;
        const int h = i & 127;
        Qs[h * 64 + m] = Qg[(size_t)m * D_EMB + h] * scale;
    }

    float acc[4][8];
#pragma unroll
    for (int i = 0; i < 4; i++)
#pragma unroll
        for (int j = 0; j < 8; j++) acc[i][j] = 0.0f;
    float Mrow[4], Lrow[4];
#pragma unroll
    for (int i = 0; i < 4; i++) {
        Mrow[i] = -1e30f;
        Lrow[i] = 0.0f;
    }

    for (int s0 = 0; s0 < T_SEQ; s0 += 64) {
        __syncthreads();  // protect Qs (first iter) and Ks/Vs from prior readers
        const float* Kg = g_K + (size_t)s0 * D_EMB + n * HD;
        const float* Vg = g_V + (size_t)s0 * D_EMB + n * HD;
        for (int i = tid; i < 64 * HD; i += 256) {
            const int s = i >> 7;
            const int h = i & 127;
            Ks[h * 64 + s] = Kg[(size_t)s * D_EMB + h];
            Vs[s * HD + h] = Vg[(size_t)s * D_EMB + h];
        }
        __syncthreads();

        // S = (Q*scale) @ K^T over h = 0..127
        float S[4][4];
#pragma unroll
        for (int i = 0; i < 4; i++)
#pragma unroll
            for (int j = 0; j < 4; j++) S[i][j] = 0.0f;
#pragma unroll 4
        for (int h = 0; h < HD; h++) {
            float qa[4], kb[4];
#pragma unroll
            for (int i = 0; i < 4; i++) qa[i] = Qs[h * 64 + ty * 4 + i];
#pragma unroll
            for (int j = 0; j < 4; j++) kb[j] = Ks[h * 64 + tx * 4 + j];
#pragma unroll
            for (int i = 0; i < 4; i++)
#pragma unroll
                for (int j = 0; j < 4; j++)
                    S[i][j] = fmaf(qa[i], kb[j], S[i][j]);
        }

        // Online softmax: per-row max over the 64-wide tile.
        float tmax[4];
#pragma unroll
        for (int i = 0; i < 4; i++) {
            tmax[i] = fmaxf(fmaxf(S[i][0], S[i][1]), fmaxf(S[i][2], S[i][3]));
        }
#pragma unroll
        for (int off = 1; off < 16; off <<= 1)
#pragma unroll
            for (int i = 0; i < 4; i++)
                tmax[i] = fmaxf(tmax[i],
                                __shfl_xor_sync(0xffffffffu, tmax[i], off));

        float Mnew[4], alphav[4], tsum[4];
#pragma unroll
        for (int i = 0; i < 4; i++) {
            Mnew[i] = fmaxf(Mrow[i], tmax[i]);
            alphav[i] = __expf(Mrow[i] - Mnew[i]);
            tsum[i] = 0.0f;
        }
#pragma unroll
        for (int i = 0; i < 4; i++)
#pragma unroll
            for (int j = 0; j < 4; j++) {
                const float p = __expf(S[i][j] - Mnew[i]);
                Ps[(tx * 4 + j) * 68 + ty * 4 + i] = p;
                tsum[i] += p;
            }
#pragma unroll
        for (int off = 1; off < 16; off <<= 1)
#pragma unroll
            for (int i = 0; i < 4; i++)
                tsum[i] += __shfl_xor_sync(0xffffffffu, tsum[i], off);
#pragma unroll
        for (int i = 0; i < 4; i++) {
            Lrow[i] = Lrow[i] * alphav[i] + tsum[i];
            Mrow[i] = Mnew[i];
#pragma unroll
            for (int j = 0; j < 8; j++) acc[i][j] *= alphav[i];
        }
        __syncthreads();  // Ps visible to all

        // O += P @ V
#pragma unroll 4
        for (int s = 0; s < 64; s++) {
            float p_[4], v_[8];
#pragma unroll
            for (int i = 0; i < 4; i++) p_[i] = Ps[s * 68 + ty * 4 + i];
#pragma unroll
            for (int j = 0; j < 8; j++) v_[j] = Vs[s * HD + tx * 8 + j];
#pragma unroll
            for (int i = 0; i < 4; i++)
#pragma unroll
                for (int j = 0; j < 8; j++)
                    acc[i][j] = fmaf(p_[i], v_[j], acc[i][j]);
        }
    }

    float* Rg = g_R + (size_t)m0 * D_EMB + n * HD;
#pragma unroll
    for (int i = 0; i < 4; i++) {
        const float inv = 1.0f / Lrow[i];
#pragma unroll
        for (int j = 0; j < 8; j++)
            Rg[(size_t)(ty * 4 + i) * D_EMB + tx * 8 + j] = acc[i][j] * inv;
    }
}

// ---------------------------------------------------------------------------
extern "C" void kernel_launch(void* const* d_in, const int* in_sizes, int n_in,
                              void* d_out, int out_size) {
    const float* X  = (const float*)d_in[0];
    const float* Wq = (const float*)d_in[1];
    const float* Wk = (const float*)d_in[2];
    const float* Wv = (const float*)d_in[3];
    const float* Wo = (const float*)d_in[4];
    float* out = (float*)d_out;

    float *qp, *kp, *vp, *rp;
    cudaGetSymbolAddress((void**)&qp, g_Q);
    cudaGetSymbolAddress((void**)&kp, g_K);
    cudaGetSymbolAddress((void**)&vp, g_V);
    cudaGetSymbolAddress((void**)&rp, g_R);

    const dim3 gb(D_EMB / 64, T_SEQ / 128);

    // QKV projections into (t, n*h) concat layout
    gemm128x64<1><<<gb, 256>>>(X, Wq, qp, T_SEQ, D_EMB, D_EMB);
    gemm128x64<1><<<gb, 256>>>(X, Wk, kp, T_SEQ, D_EMB, D_EMB);
    gemm128x64<1><<<gb, 256>>>(X, Wv, vp, T_SEQ, D_EMB, D_EMB);

    // Flash attention: 32 query tiles x 16 heads
    const int smem = (HD * 64 + HD * 64 + 64 * HD + 64 * 68) * (int)sizeof(float);
    cudaFuncSetAttribute(attn_kernel,
                         cudaFuncAttributeMaxDynamicSharedMemorySize, smem);
    attn_kernel<<<dim3(T_SEQ / 64, NHEADS), 256, smem>>>();

    // Output projection: X_cat (== g_R) @ W_out
    gemm128x64<0><<<gb, 256>>>(rp, Wo, out, T_SEQ, D_EMB, D_EMB);
}

// round 3
// speedup vs baseline: 1.5341x; 1.5341x over previous
#include <cuda_runtime.h>
#include <cuda_bf16.h>
#include <stdint.h>
#include <math.h>

#define T_SEQ 2048
#define D_EMB 2048
#define HD    128
#define NHEADS 16

// ---------------- scratch (no allocs allowed) ----------------
__device__ float g_Q[T_SEQ * D_EMB];
__device__ float g_K[T_SEQ * D_EMB];
__device__ float g_V[T_SEQ * D_EMB];
__device__ float g_R[T_SEQ * D_EMB];

__device__ __nv_bfloat16 g_Xh[T_SEQ * D_EMB], g_Xl[T_SEQ * D_EMB];
__device__ __nv_bfloat16 g_Rh[T_SEQ * D_EMB], g_Rl[T_SEQ * D_EMB];
// transposed weights, [N=out][K=in] K-major, hi/lo split
__device__ __nv_bfloat16 g_Wqh[D_EMB * D_EMB], g_Wql[D_EMB * D_EMB];
__device__ __nv_bfloat16 g_Wkh[D_EMB * D_EMB], g_Wkl[D_EMB * D_EMB];
__device__ __nv_bfloat16 g_Wvh[D_EMB * D_EMB], g_Wvl[D_EMB * D_EMB];
__device__ __nv_bfloat16 g_Woh[D_EMB * D_EMB], g_Wol[D_EMB * D_EMB];

// ---------------- PTX helpers (base sm_103-legal only) ----------------
__device__ __forceinline__ uint32_t smem_u32(const void* p) {
    uint32_t a;
    asm("{ .reg .u64 t; cvta.to.shared.u64 t, %1; cvt.u32.u64 %0, t; }"
        : "=r"(a) : "l"(p));
    return a;
}
#define CP_ASYNC16(dst, src) \
    asm volatile("cp.async.cg.shared.global [%0], [%1], 16;" :: "r"(dst), "l"(src))
#define CP_COMMIT() asm volatile("cp.async.commit_group;" ::: "memory")
#define CP_WAIT(n) asm volatile("cp.async.wait_group %0;" :: "n"(n) : "memory")

__device__ __forceinline__ void ldsm_x4(uint32_t& r0, uint32_t& r1, uint32_t& r2,
                                        uint32_t& r3, uint32_t addr) {
    asm volatile("ldmatrix.sync.aligned.m8n8.x4.shared.b16 {%0,%1,%2,%3}, [%4];"
                 : "=r"(r0), "=r"(r1), "=r"(r2), "=r"(r3) : "r"(addr));
}
__device__ __forceinline__ void mma16816(float* c, const uint32_t* a,
                                         const uint32_t* b) {
    asm volatile(
        "mma.sync.aligned.m16n8k16.row.col.f32.bf16.bf16.f32 "
        "{%0,%1,%2,%3}, {%4,%5,%6,%7}, {%8,%9}, {%0,%1,%2,%3};"
        : "+f"(c[0]), "+f"(c[1]), "+f"(c[2]), "+f"(c[3])
        : "r"(a[0]), "r"(a[1]), "r"(a[2]), "r"(a[3]), "r"(b[0]), "r"(b[1]));
}

// ---------------- conversion kernels ----------------
__global__ __launch_bounds__(256) void convA(const float* __restrict__ A,
                                             __nv_bfloat16* __restrict__ H,
                                             __nv_bfloat16* __restrict__ L) {
    const int i = blockIdx.x * 256 + threadIdx.x;
    float4 v = reinterpret_cast<const float4*>(A)[i];
    __nv_bfloat16 h[4], l[4];
    const float x[4] = {v.x, v.y, v.z, v.w};
#pragma unroll
    for (int j = 0; j < 4; j++) {
        h[j] = __float2bfloat16(x[j]);
        l[j] = __float2bfloat16(x[j] - __bfloat162float(h[j]));
    }
    reinterpret_cast<uint2*>(H)[i] = *reinterpret_cast<uint2*>(h);
    reinterpret_cast<uint2*>(L)[i] = *reinterpret_cast<uint2*>(l);
}

// W[(head) n][k][j] -> Bt[n*hd + j][k] hi/lo
__global__ __launch_bounds__(256) void convW(const float* __restrict__ W,
                                             __nv_bfloat16* __restrict__ H,
                                             __nv_bfloat16* __restrict__ L, int hd) {
    __shared__ float t[32][33];
    const int n = blockIdx.z;
    const int j0 = blockIdx.x * 32, k0 = blockIdx.y * 32;
    const int tx = threadIdx.x, ty = threadIdx.y;
    const float* Wn = W + (size_t)n * D_EMB * hd;
#pragma unroll
    for (int y = ty; y < 32; y += 8) t[y][tx] = Wn[(size_t)(k0 + y) * hd + j0 + tx];
    __syncthreads();
#pragma unroll
    for (int y = ty; y < 32; y += 8) {
        const float v = t[tx][y];
        const __nv_bfloat16 h = __float2bfloat16(v);
        const __nv_bfloat16 l = __float2bfloat16(v - __bfloat162float(h));
        const size_t o = (size_t)(n * hd + j0 + y) * D_EMB + k0 + tx;
        H[o] = h;
        L[o] = l;
    }
}

// ---------------- split-bf16 HMMA GEMM ----------------
// C[2048,2048] fp32 = (Ah+Al) @ (Bh+Bl)^T, B stored [N][K] K-major (row.col mma).
// CTA tile 128x128x32, 8 warps (4m x 2n), warp tile 32m x 64n.
// Smem per stage 32KB: [Ah 8K][Al 8K][Bh 8K][Bl 8K], double buffered (64KB).
#define BM 128
#define BN 128
#define BK 32
#define GEMM_SMEM 65536

// swizzled 16B-chunk address: row-major [rows][4 chunks], chunk ^= (row>>1)&3
__device__ __forceinline__ uint32_t swz(uint32_t base, int row, int chunk) {
    return base + (((row << 2) + (chunk ^ ((row >> 1) & 3))) << 4);
}

__device__ __forceinline__ void stage_tile(uint32_t sbase,
                                           const __nv_bfloat16* __restrict__ g,
                                           int row0, int k0, int tid) {
    // one 128x32 bf16 tile = 512 16B chunks, 256 threads x 2
#pragma unroll
    for (int u = tid; u < 512; u += 256) {
        const int row = u >> 2, ch = u & 3;
        const uint32_t dst = swz(sbase, row, ch);
        const __nv_bfloat16* src = g + (size_t)(row0 + row) * D_EMB + k0 + ch * 8;
        CP_ASYNC16(dst, src);
    }
}

__global__ __launch_bounds__(256, 1) void gemm_mma(
    const __nv_bfloat16* __restrict__ Ah, const __nv_bfloat16* __restrict__ Al,
    const __nv_bfloat16* __restrict__ Bh, const __nv_bfloat16* __restrict__ Bl,
    float* __restrict__ C) {
    extern __shared__ char sm[];
    const uint32_t sb = smem_u32(sm);
    const int tid = threadIdx.x;
    const int lane = tid & 31;
    const int wid = tid >> 5;
    const int wm = wid & 3;   // warp m index (4)
    const int wn = wid >> 2;  // warp n index (2)
    const int bm = blockIdx.y * BM;
    const int bn = blockIdx.x * BN;

    float acc[2][8][4];
#pragma unroll
    for (int mt = 0; mt < 2; mt++)
#pragma unroll
        for (int nt = 0; nt < 8; nt++)
#pragma unroll
            for (int e = 0; e < 4; e++) acc[mt][nt][e] = 0.0f;

    const int lr = lane & 7;
    const int lg = lane >> 3;  // ldmatrix group 0..3

    // stage 0
    {
        const uint32_t s0 = sb;
        stage_tile(s0 + 0,     Ah, bm, 0, tid);
        stage_tile(s0 + 8192,  Al, bm, 0, tid);
        stage_tile(s0 + 16384, Bh, bn, 0, tid);
        stage_tile(s0 + 24576, Bl, bn, 0, tid);
        CP_COMMIT();
    }

    const int NITER = D_EMB / BK;  // 64
    for (int c = 0; c < NITER; c++) {
        const int b = c & 1;
        if (c + 1 < NITER) {
            const uint32_t s1 = sb + (b ^ 1) * 32768;
            const int k0 = (c + 1) * BK;
            stage_tile(s1 + 0,     Ah, bm, k0, tid);
            stage_tile(s1 + 8192,  Al, bm, k0, tid);
            stage_tile(s1 + 16384, Bh, bn, k0, tid);
            stage_tile(s1 + 24576, Bl, bn, k0, tid);
            CP_COMMIT();
            CP_WAIT(1);
        } else {
            CP_WAIT(0);
        }
        __syncthreads();

        const uint32_t sAh = sb + b * 32768;
        const uint32_t sAl = sAh + 8192;
        const uint32_t sBh = sAh + 16384;
        const uint32_t sBl = sAh + 24576;

#pragma unroll
        for (int kk = 0; kk < 2; kk++) {
            // A fragments: per m-tile, x4 (groups: rows m..m+7 c | m+8.. c | m.. c+1 | m+8 c+1)
            uint32_t ah[2][4], al[2][4];
#pragma unroll
            for (int mt = 0; mt < 2; mt++) {
                const int row = wm * 32 + mt * 16 + lr + (lg & 1) * 8;
                const int ch = kk * 2 + (lg >> 1);
                ldsm_x4(ah[mt][0], ah[mt][1], ah[mt][2], ah[mt][3],
                        swz(sAh, row, ch));
                ldsm_x4(al[mt][0], al[mt][1], al[mt][2], al[mt][3],
                        swz(sAl, row, ch));
            }
            // B fragments: pairs of n-tiles via x4
            // groups: n.. c | n.. c+1 | n+8.. c | n+8.. c+1
            uint32_t bh[8][2], bl[8][2];
#pragma unroll
            for (int np = 0; np < 4; np++) {
                const int row = wn * 64 + np * 16 + lr + (lg >> 1) * 8;
                const int ch = kk * 2 + (lg & 1);
                ldsm_x4(bh[np * 2][0], bh[np * 2][1], bh[np * 2 + 1][0],
                        bh[np * 2 + 1][1], swz(sBh, row, ch));
                ldsm_x4(bl[np * 2][0], bl[np * 2][1], bl[np * 2 + 1][0],
                        bl[np * 2 + 1][1], swz(sBl, row, ch));
            }
#pragma unroll
            for (int mt = 0; mt < 2; mt++)
#pragma unroll
                for (int nt = 0; nt < 8; nt++) {
                    mma16816(acc[mt][nt], ah[mt], bh[nt]);
                    mma16816(acc[mt][nt], ah[mt], bl[nt]);
                    mma16816(acc[mt][nt], al[mt], bh[nt]);
                }
        }
        __syncthreads();
    }

    // epilogue: direct float2 stores
#pragma unroll
    for (int mt = 0; mt < 2; mt++) {
        const int row = bm + wm * 32 + mt * 16 + (lane >> 2);
#pragma unroll
        for (int nt = 0; nt < 8; nt++) {
            const int col = bn + wn * 64 + nt * 8 + (lane & 3) * 2;
            *reinterpret_cast<float2*>(&C[(size_t)row * D_EMB + col]) =
                make_float2(acc[mt][nt][0], acc[mt][nt][1]);
            *reinterpret_cast<float2*>(&C[(size_t)(row + 8) * D_EMB + col]) =
                make_float2(acc[mt][nt][2], acc[mt][nt][3]);
        }
    }
}

// ---------------------------------------------------------------------------
// Flash attention (fp32, online softmax) — unchanged from round 1 (passing).
// ---------------------------------------------------------------------------
__global__ __launch_bounds__(256) void attn_kernel() {
    extern __shared__ float smf[];
    float* Qs = smf;
    float* Ks = Qs + HD * 64;
    float* Vs = Ks + HD * 64;
    float* Ps = Vs + 64 * HD;

    const int n = blockIdx.y;
    const int m0 = blockIdx.x * 64;
    const int tid = threadIdx.x;
    const int tx = tid & 15;
    const int ty = tid >> 4;
    const float scale = 0.08838834764831843f;

    const float* Qg = g_Q + (size_t)m0 * D_EMB + n * HD;
    for (int i = tid; i < 64 * HD; i += 256) {
        const int m = i >> 7;
        const int h = i & 127;
        Qs[h * 64 + m] = Qg[(size_t)m * D_EMB + h] * scale;
    }

    float acc[4][8];
#pragma unroll
    for (int i = 0; i < 4; i++)
#pragma unroll
        for (int j = 0; j < 8; j++) acc[i][j] = 0.0f;
    float Mrow[4], Lrow[4];
#pragma unroll
    for (int i = 0; i < 4; i++) {
        Mrow[i] = -1e30f;
        Lrow[i] = 0.0f;
    }

    for (int s0 = 0; s0 < T_SEQ; s0 += 64) {
        __syncthreads();
        const float* Kg = g_K + (size_t)s0 * D_EMB + n * HD;
        const float* Vg = g_V + (size_t)s0 * D_EMB + n * HD;
        for (int i = tid; i < 64 * HD; i += 256) {
            const int s = i >> 7;
            const int h = i & 127;
            Ks[h * 64 + s] = Kg[(size_t)s * D_EMB + h];
            Vs[s * HD + h] = Vg[(size_t)s * D_EMB + h];
        }
        __syncthreads();

        float S[4][4];
#pragma unroll
        for (int i = 0; i < 4; i++)
#pragma unroll
            for (int j = 0; j < 4; j++) S[i][j] = 0.0f;
#pragma unroll 4
        for (int h = 0; h < HD; h++) {
            float qa[4], kb[4];
#pragma unroll
            for (int i = 0; i < 4; i++) qa[i] = Qs[h * 64 + ty * 4 + i];
#pragma unroll
            for (int j = 0; j < 4; j++) kb[j] = Ks[h * 64 + tx * 4 + j];
#pragma unroll
            for (int i = 0; i < 4; i++)
#pragma unroll
                for (int j = 0; j < 4; j++)
                    S[i][j] = fmaf(qa[i], kb[j], S[i][j]);
        }

        float tmax[4];
#pragma unroll
        for (int i = 0; i < 4; i++)
            tmax[i] = fmaxf(fmaxf(S[i][0], S[i][1]), fmaxf(S[i][2], S[i][3]));
#pragma unroll
        for (int off = 1; off < 16; off <<= 1)
#pragma unroll
            for (int i = 0; i < 4; i++)
                tmax[i] = fmaxf(tmax[i], __shfl_xor_sync(0xffffffffu, tmax[i], off));

        float Mnew[4], alphav[4], tsum[4];
#pragma unroll
        for (int i = 0; i < 4; i++) {
            Mnew[i] = fmaxf(Mrow[i], tmax[i]);
            alphav[i] = __expf(Mrow[i] - Mnew[i]);
            tsum[i] = 0.0f;
        }
#pragma unroll
        for (int i = 0; i < 4; i++)
#pragma unroll
            for (int j = 0; j < 4; j++) {
                const float p = __expf(S[i][j] - Mnew[i]);
                Ps[(tx * 4 + j) * 68 + ty * 4 + i] = p;
                tsum[i] += p;
            }
#pragma unroll
        for (int off = 1; off < 16; off <<= 1)
#pragma unroll
            for (int i = 0; i < 4; i++)
                tsum[i] += __shfl_xor_sync(0xffffffffu, tsum[i], off);
#pragma unroll
        for (int i = 0; i < 4; i++) {
            Lrow[i] = Lrow[i] * alphav[i] + tsum[i];
            Mrow[i] = Mnew[i];
#pragma unroll
            for (int j = 0; j < 8; j++) acc[i][j] *= alphav[i];
        }
        __syncthreads();

#pragma unroll 4
        for (int s = 0; s < 64; s++) {
            float p_[4], v_[8];
#pragma unroll
            for (int i = 0; i < 4; i++) p_[i] = Ps[s * 68 + ty * 4 + i];
#pragma unroll
            for (int j = 0; j < 8; j++) v_[j] = Vs[s * HD + tx * 8 + j];
#pragma unroll
            for (int i = 0; i < 4; i++)
#pragma unroll
                for (int j = 0; j < 8; j++)
                    acc[i][j] = fmaf(p_[i], v_[j], acc[i][j]);
        }
    }

    float* Rg = g_R + (size_t)m0 * D_EMB + n * HD;
#pragma unroll
    for (int i = 0; i < 4; i++) {
        const float inv = 1.0f / Lrow[i];
#pragma unroll
        for (int j = 0; j < 8; j++)
            Rg[(size_t)(ty * 4 + i) * D_EMB + tx * 8 + j] = acc[i][j] * inv;
    }
}

// ---------------------------------------------------------------------------
extern "C" void kernel_launch(void* const* d_in, const int* in_sizes, int n_in,
                              void* d_out, int out_size) {
    const float* X  = (const float*)d_in[0];
    const float* Wq = (const float*)d_in[1];
    const float* Wk = (const float*)d_in[2];
    const float* Wv = (const float*)d_in[3];
    const float* Wo = (const float*)d_in[4];
    float* out = (float*)d_out;

    float *qp, *kp, *vp, *rp;
    cudaGetSymbolAddress((void**)&qp, g_Q);
    cudaGetSymbolAddress((void**)&kp, g_K);
    cudaGetSymbolAddress((void**)&vp, g_V);
    cudaGetSymbolAddress((void**)&rp, g_R);
    __nv_bfloat16 *xh, *xl, *rh, *rl;
    __nv_bfloat16 *wqh, *wql, *wkh, *wkl, *wvh, *wvl, *woh, *wol;
    cudaGetSymbolAddress((void**)&xh, g_Xh);
    cudaGetSymbolAddress((void**)&xl, g_Xl);
    cudaGetSymbolAddress((void**)&rh, g_Rh);
    cudaGetSymbolAddress((void**)&rl, g_Rl);
    cudaGetSymbolAddress((void**)&wqh, g_Wqh);
    cudaGetSymbolAddress((void**)&wql, g_Wql);
    cudaGetSymbolAddress((void**)&wkh, g_Wkh);
    cudaGetSymbolAddress((void**)&wkl, g_Wkl);
    cudaGetSymbolAddress((void**)&wvh, g_Wvh);
    cudaGetSymbolAddress((void**)&wvl, g_Wvl);
    cudaGetSymbolAddress((void**)&woh, g_Woh);
    cudaGetSymbolAddress((void**)&wol, g_Wol);

    // input conversions / splits
    convA<<<T_SEQ * D_EMB / 4 / 256, 256>>>(X, xh, xl);
    convW<<<dim3(HD / 32, D_EMB / 32, NHEADS), dim3(32, 8)>>>(Wq, wqh, wql, HD);
    convW<<<dim3(HD / 32, D_EMB / 32, NHEADS), dim3(32, 8)>>>(Wk, wkh, wkl, HD);
    convW<<<dim3(HD / 32, D_EMB / 32, NHEADS), dim3(32, 8)>>>(Wv, wvh, wvl, HD);
    convW<<<dim3(D_EMB / 32, D_EMB / 32, 1), dim3(32, 8)>>>(Wo, woh, wol, D_EMB);

    // HMMA projection GEMMs
    cudaFuncSetAttribute(gemm_mma, cudaFuncAttributeMaxDynamicSharedMemorySize,
                         GEMM_SMEM);
    const dim3 gg(D_EMB / BN, T_SEQ / BM);
    gemm_mma<<<gg, 256, GEMM_SMEM>>>(xh, xl, wqh, wql, qp);
    gemm_mma<<<gg, 256, GEMM_SMEM>>>(xh, xl, wkh, wkl, kp);
    gemm_mma<<<gg, 256, GEMM_SMEM>>>(xh, xl, wvh, wvl, vp);

    // flash attention (fp32)
    const int smem = (HD * 64 + HD * 64 + 64 * HD + 64 * 68) * (int)sizeof(float);
    cudaFuncSetAttribute(attn_kernel,
                         cudaFuncAttributeMaxDynamicSharedMemorySize, smem);
    attn_kernel<<<dim3(T_SEQ / 64, NHEADS), 256, smem>>>();

    // out-projection
    convA<<<T_SEQ * D_EMB / 4 / 256, 256>>>(rp, rh, rl);
    gemm_mma<<<gg, 256, GEMM_SMEM>>>(rh, rl, woh, wol, out);
}

// round 4
// speedup vs baseline: 2.4663x; 1.6077x over previous
#include <cuda_runtime.h>
#include <cuda_bf16.h>
#include <stdint.h>
#include <math.h>

#define T_SEQ 2048
#define D_EMB 2048
#define HD    128
#define NHEADS 16

// ---------------- scratch (no allocs allowed) ----------------
__device__ float g_Q[T_SEQ * D_EMB];
__device__ float g_K[T_SEQ * D_EMB];
__device__ float g_V[T_SEQ * D_EMB];
__device__ float g_R[T_SEQ * D_EMB];

__device__ __nv_bfloat16 g_Xh[T_SEQ * D_EMB], g_Xl[T_SEQ * D_EMB];
__device__ __nv_bfloat16 g_Rh[T_SEQ * D_EMB], g_Rl[T_SEQ * D_EMB];
// transposed weights, [N=out][K=in] K-major, hi/lo split
__device__ __nv_bfloat16 g_Wqh[D_EMB * D_EMB], g_Wql[D_EMB * D_EMB];
__device__ __nv_bfloat16 g_Wkh[D_EMB * D_EMB], g_Wkl[D_EMB * D_EMB];
__device__ __nv_bfloat16 g_Wvh[D_EMB * D_EMB], g_Wvl[D_EMB * D_EMB];
__device__ __nv_bfloat16 g_Woh[D_EMB * D_EMB], g_Wol[D_EMB * D_EMB];
// attention operands: Q/K split (t, n*h); V split transposed [n*h][t]
__device__ __nv_bfloat16 g_Qbh[T_SEQ * D_EMB], g_Qbl[T_SEQ * D_EMB];
__device__ __nv_bfloat16 g_Kbh[T_SEQ * D_EMB], g_Kbl[T_SEQ * D_EMB];
__device__ __nv_bfloat16 g_Vth[D_EMB * T_SEQ], g_Vtl[D_EMB * T_SEQ];

// ---------------- PTX helpers (base sm_103-legal only) ----------------
__device__ __forceinline__ uint32_t smem_u32(const void* p) {
    uint32_t a;
    asm("{ .reg .u64 t; cvta.to.shared.u64 t, %1; cvt.u32.u64 %0, t; }"
        : "=r"(a) : "l"(p));
    return a;
}
#define CP_ASYNC16(dst, src) \
    asm volatile("cp.async.cg.shared.global [%0], [%1], 16;" :: "r"(dst), "l"(src))
#define CP_COMMIT() asm volatile("cp.async.commit_group;" ::: "memory")
#define CP_WAIT(n) asm volatile("cp.async.wait_group %0;" :: "n"(n) : "memory")

__device__ __forceinline__ void ldsm_x4(uint32_t& r0, uint32_t& r1, uint32_t& r2,
                                        uint32_t& r3, uint32_t addr) {
    asm volatile("ldmatrix.sync.aligned.m8n8.x4.shared.b16 {%0,%1,%2,%3}, [%4];"
                 : "=r"(r0), "=r"(r1), "=r"(r2), "=r"(r3) : "r"(addr));
}
__device__ __forceinline__ void mma16816(float* c, const uint32_t* a,
                                         const uint32_t* b) {
    asm volatile(
        "mma.sync.aligned.m16n8k16.row.col.f32.bf16.bf16.f32 "
        "{%0,%1,%2,%3}, {%4,%5,%6,%7}, {%8,%9}, {%0,%1,%2,%3};"
        : "+f"(c[0]), "+f"(c[1]), "+f"(c[2]), "+f"(c[3])
        : "r"(a[0]), "r"(a[1]), "r"(a[2]), "r"(a[3]), "r"(b[0]), "r"(b[1]));
}
__device__ __forceinline__ uint32_t pack_hi_lo(float x, float y, uint32_t& lo) {
    const __nv_bfloat16 hx = __float2bfloat16(x), hy = __float2bfloat16(y);
    const __nv_bfloat16 lx = __float2bfloat16(x - __bfloat162float(hx));
    const __nv_bfloat16 ly = __float2bfloat16(y - __bfloat162float(hy));
    lo = (uint32_t)*(const uint16_t*)&lx | ((uint32_t)*(const uint16_t*)&ly << 16);
    return (uint32_t)*(const uint16_t*)&hx | ((uint32_t)*(const uint16_t*)&hy << 16);
}

// ---------------- conversion kernels ----------------
__global__ __launch_bounds__(256) void convA(const float* __restrict__ A,
                                             __nv_bfloat16* __restrict__ H,
                                             __nv_bfloat16* __restrict__ L,
                                             float scale) {
    const int i = blockIdx.x * 256 + threadIdx.x;
    float4 v = reinterpret_cast<const float4*>(A)[i];
    __nv_bfloat16 h[4], l[4];
    const float x[4] = {v.x * scale, v.y * scale, v.z * scale, v.w * scale};
#pragma unroll
    for (int j = 0; j < 4; j++) {
        h[j] = __float2bfloat16(x[j]);
        l[j] = __float2bfloat16(x[j] - __bfloat162float(h[j]));
    }
    reinterpret_cast<uint2*>(H)[i] = *reinterpret_cast<uint2*>(h);
    reinterpret_cast<uint2*>(L)[i] = *reinterpret_cast<uint2*>(l);
}

// W[(head) n][k][j] -> Bt[n*hd + j][k] hi/lo  (also used as plain transposer)
__global__ __launch_bounds__(256) void convW(const float* __restrict__ W,
                                             __nv_bfloat16* __restrict__ H,
                                             __nv_bfloat16* __restrict__ L, int hd) {
    __shared__ float t[32][33];
    const int n = blockIdx.z;
    const int j0 = blockIdx.x * 32, k0 = blockIdx.y * 32;
    const int tx = threadIdx.x, ty = threadIdx.y;
    const float* Wn = W + (size_t)n * D_EMB * hd;
#pragma unroll
    for (int y = ty; y < 32; y += 8) t[y][tx] = Wn[(size_t)(k0 + y) * hd + j0 + tx];
    __syncthreads();
#pragma unroll
    for (int y = ty; y < 32; y += 8) {
        const float v = t[tx][y];
        const __nv_bfloat16 h = __float2bfloat16(v);
        const __nv_bfloat16 l = __float2bfloat16(v - __bfloat162float(h));
        const size_t o = (size_t)(n * hd + j0 + y) * D_EMB + k0 + tx;
        H[o] = h;
        L[o] = l;
    }
}

// ---------------- split-bf16 HMMA GEMM (validated round 3) ----------------
#define BM 128
#define BN 128
#define BK 32
#define GEMM_SMEM 65536

__device__ __forceinline__ uint32_t swz(uint32_t base, int row, int chunk) {
    return base + (((row << 2) + (chunk ^ ((row >> 1) & 3))) << 4);
}

__device__ __forceinline__ void stage_tile(uint32_t sbase,
                                           const __nv_bfloat16* __restrict__ g,
                                           int row0, int k0, int tid) {
#pragma unroll
    for (int u = tid; u < 512; u += 256) {
        const int row = u >> 2, ch = u & 3;
        const uint32_t dst = swz(sbase, row, ch);
        const __nv_bfloat16* src = g + (size_t)(row0 + row) * D_EMB + k0 + ch * 8;
        CP_ASYNC16(dst, src);
    }
}

__global__ __launch_bounds__(256, 1) void gemm_mma(
    const __nv_bfloat16* __restrict__ Ah, const __nv_bfloat16* __restrict__ Al,
    const __nv_bfloat16* __restrict__ Bh, const __nv_bfloat16* __restrict__ Bl,
    float* __restrict__ C) {
    extern __shared__ char sm[];
    const uint32_t sb = smem_u32(sm);
    const int tid = threadIdx.x;
    const int lane = tid & 31;
    const int wid = tid >> 5;
    const int wm = wid & 3;
    const int wn = wid >> 2;
    const int bm = blockIdx.y * BM;
    const int bn = blockIdx.x * BN;

    float acc[2][8][4];
#pragma unroll
    for (int mt = 0; mt < 2; mt++)
#pragma unroll
        for (int nt = 0; nt < 8; nt++)
#pragma unroll
            for (int e = 0; e < 4; e++) acc[mt][nt][e] = 0.0f;

    const int lr = lane & 7;
    const int lg = lane >> 3;

    {
        const uint32_t s0 = sb;
        stage_tile(s0 + 0,     Ah, bm, 0, tid);
        stage_tile(s0 + 8192,  Al, bm, 0, tid);
        stage_tile(s0 + 16384, Bh, bn, 0, tid);
        stage_tile(s0 + 24576, Bl, bn, 0, tid);
        CP_COMMIT();
    }

    const int NITER = D_EMB / BK;
    for (int c = 0; c < NITER; c++) {
        const int b = c & 1;
        if (c + 1 < NITER) {
            const uint32_t s1 = sb + (b ^ 1) * 32768;
            const int k0 = (c + 1) * BK;
            stage_tile(s1 + 0,     Ah, bm, k0, tid);
            stage_tile(s1 + 8192,  Al, bm, k0, tid);
            stage_tile(s1 + 16384, Bh, bn, k0, tid);
            stage_tile(s1 + 24576, Bl, bn, k0, tid);
            CP_COMMIT();
            CP_WAIT(1);
        } else {
            CP_WAIT(0);
        }
        __syncthreads();

        const uint32_t sAh = sb + b * 32768;
        const uint32_t sAl = sAh + 8192;
        const uint32_t sBh = sAh + 16384;
        const uint32_t sBl = sAh + 24576;

#pragma unroll
        for (int kk = 0; kk < 2; kk++) {
            uint32_t ah[2][4], al[2][4];
#pragma unroll
            for (int mt = 0; mt < 2; mt++) {
                const int row = wm * 32 + mt * 16 + lr + (lg & 1) * 8;
                const int ch = kk * 2 + (lg >> 1);
                ldsm_x4(ah[mt][0], ah[mt][1], ah[mt][2], ah[mt][3],
                        swz(sAh, row, ch));
                ldsm_x4(al[mt][0], al[mt][1], al[mt][2], al[mt][3],
                        swz(sAl, row, ch));
            }
            uint32_t bh[8][2], bl[8][2];
#pragma unroll
            for (int np = 0; np < 4; np++) {
                const int row = wn * 64 + np * 16 + lr + (lg >> 1) * 8;
                const int ch = kk * 2 + (lg & 1);
                ldsm_x4(bh[np * 2][0], bh[np * 2][1], bh[np * 2 + 1][0],
                        bh[np * 2 + 1][1], swz(sBh, row, ch));
                ldsm_x4(bl[np * 2][0], bl[np * 2][1], bl[np * 2 + 1][0],
                        bl[np * 2 + 1][1], swz(sBl, row, ch));
            }
#pragma unroll
            for (int mt = 0; mt < 2; mt++)
#pragma unroll
                for (int nt = 0; nt < 8; nt++) {
                    mma16816(acc[mt][nt], ah[mt], bh[nt]);
                    mma16816(acc[mt][nt], ah[mt], bl[nt]);
                    mma16816(acc[mt][nt], al[mt], bh[nt]);
                }
        }
        __syncthreads();
    }

#pragma unroll
    for (int mt = 0; mt < 2; mt++) {
        const int row = bm + wm * 32 + mt * 16 + (lane >> 2);
#pragma unroll
        for (int nt = 0; nt < 8; nt++) {
            const int col = bn + wn * 64 + nt * 8 + (lane & 3) * 2;
            *reinterpret_cast<float2*>(&C[(size_t)row * D_EMB + col]) =
                make_float2(acc[mt][nt][0], acc[mt][nt][1]);
            *reinterpret_cast<float2*>(&C[(size_t)(row + 8) * D_EMB + col]) =
                make_float2(acc[mt][nt][2], acc[mt][nt][3]);
        }
    }
}

// ---------------- HMMA flash attention (split-bf16, 3-pass) ----------------
// Block: 128 threads (4 warps), head n, 64 query rows. Warp owns 16 rows.
// smem: Qh/Ql [64][128], Kh/Kl [64][128], Vh/Vl [128][64] (V transposed).
#define ATTN_SMEM 98304

__global__ __launch_bounds__(128, 2) void attn_mma(
    const __nv_bfloat16* __restrict__ Qh, const __nv_bfloat16* __restrict__ Ql,
    const __nv_bfloat16* __restrict__ Kh, const __nv_bfloat16* __restrict__ Kl,
    const __nv_bfloat16* __restrict__ Vth, const __nv_bfloat16* __restrict__ Vtl,
    float* __restrict__ R) {
    extern __shared__ char sm[];
    const uint32_t sb = smem_u32(sm);
    const uint32_t sQh = sb, sQl = sb + 16384;
    const uint32_t sKh = sb + 32768, sKl = sb + 49152;
    const uint32_t sVh = sb + 65536, sVl = sb + 81920;

    const int n = blockIdx.y;
    const int m0 = blockIdx.x * 64;
    const int tid = threadIdx.x;
    const int lane = tid & 31;
    const int w = tid >> 5;
    const int lr = lane & 7;
    const int lg = lane >> 3;

    // stage Q (64 rows x 256B), hi+lo
    for (int u = tid; u < 1024; u += 128) {
        const int row = u >> 4, ch = u & 15;
        const uint32_t d = (uint32_t)((row * 16 + (ch ^ (row & 7))) * 16);
        const size_t g = (size_t)(m0 + row) * D_EMB + n * HD + ch * 8;
        CP_ASYNC16(sQh + d, Qh + g);
        CP_ASYNC16(sQl + d, Ql + g);
    }
    CP_COMMIT();

    float acc[16][4];
#pragma unroll
    for (int ht = 0; ht < 16; ht++)
#pragma unroll
        for (int e = 0; e < 4; e++) acc[ht][e] = 0.0f;
    float M0 = -1e30f, M1 = -1e30f, L0 = 0.0f, L1 = 0.0f;

    for (int s0 = 0; s0 < T_SEQ; s0 += 64) {
        __syncthreads();
        for (int u = tid; u < 1024; u += 128) {
            const int row = u >> 4, ch = u & 15;
            const uint32_t d = (uint32_t)((row * 16 + (ch ^ (row & 7))) * 16);
            const size_t g = (size_t)(s0 + row) * D_EMB + n * HD + ch * 8;
            CP_ASYNC16(sKh + d, Kh + g);
            CP_ASYNC16(sKl + d, Kl + g);
        }
        for (int u = tid; u < 1024; u += 128) {
            const int row = u >> 3, ch = u & 7;
            const uint32_t d = (uint32_t)((row * 8 + (ch ^ (row & 7))) * 16);
            const size_t g = (size_t)(n * HD + row) * T_SEQ + s0 + ch * 8;
            CP_ASYNC16(sVh + d, Vth + g);
            CP_ASYNC16(sVl + d, Vtl + g);
        }
        CP_COMMIT();
        CP_WAIT(0);
        __syncthreads();

        // ---- S = Q K^T (3-pass split), warp tile 16m x 64s ----
        float c[8][4];
#pragma unroll
        for (int t = 0; t < 8; t++)
#pragma unroll
            for (int e = 0; e < 4; e++) c[t][e] = 0.0f;

#pragma unroll
        for (int kk = 0; kk < 8; kk++) {
            uint32_t qh4[4], ql4[4];
            {
                const int row = w * 16 + lr + (lg & 1) * 8;
                const int ch = kk * 2 + (lg >> 1);
                const uint32_t a = (uint32_t)((row * 16 + (ch ^ (row & 7))) * 16);
                ldsm_x4(qh4[0], qh4[1], qh4[2], qh4[3], sQh + a);
                ldsm_x4(ql4[0], ql4[1], ql4[2], ql4[3], sQl + a);
            }
#pragma unroll
            for (int np = 0; np < 4; np++) {
                uint32_t kh4[4], kl4[4];
                const int row = np * 16 + lr + (lg >> 1) * 8;
                const int ch = kk * 2 + (lg & 1);
                const uint32_t a = (uint32_t)((row * 16 + (ch ^ (row & 7))) * 16);
                ldsm_x4(kh4[0], kh4[1], kh4[2], kh4[3], sKh + a);
                ldsm_x4(kl4[0], kl4[1], kl4[2], kl4[3], sKl + a);
                mma16816(c[np * 2],     qh4, &kh4[0]);
                mma16816(c[np * 2 + 1], qh4, &kh4[2]);
                mma16816(c[np * 2],     qh4, &kl4[0]);
                mma16816(c[np * 2 + 1], qh4, &kl4[2]);
                mma16816(c[np * 2],     ql4, &kh4[0]);
                mma16816(c[np * 2 + 1], ql4, &kh4[2]);
            }
        }

        // ---- online softmax (rows r = lane>>2 and r+8) ----
        float mx0 = -1e30f, mx1 = -1e30f;
#pragma unroll
        for (int t = 0; t < 8; t++) {
            mx0 = fmaxf(mx0, fmaxf(c[t][0], c[t][1]));
            mx1 = fmaxf(mx1, fmaxf(c[t][2], c[t][3]));
        }
        mx0 = fmaxf(mx0, __shfl_xor_sync(0xffffffffu, mx0, 1));
        mx0 = fmaxf(mx0, __shfl_xor_sync(0xffffffffu, mx0, 2));
        mx1 = fmaxf(mx1, __shfl_xor_sync(0xffffffffu, mx1, 1));
        mx1 = fmaxf(mx1, __shfl_xor_sync(0xffffffffu, mx1, 2));

        const float Mn0 = fmaxf(M0, mx0), Mn1 = fmaxf(M1, mx1);
        const float a0 = __expf(M0 - Mn0), a1 = __expf(M1 - Mn1);
        float sum0 = 0.0f, sum1 = 0.0f;
#pragma unroll
        for (int t = 0; t < 8; t++) {
            c[t][0] = __expf(c[t][0] - Mn0);
            c[t][1] = __expf(c[t][1] - Mn0);
            c[t][2] = __expf(c[t][2] - Mn1);
            c[t][3] = __expf(c[t][3] - Mn1);
            sum0 += c[t][0] + c[t][1];
            sum1 += c[t][2] + c[t][3];
        }
        sum0 += __shfl_xor_sync(0xffffffffu, sum0, 1);
        sum0 += __shfl_xor_sync(0xffffffffu, sum0, 2);
        sum1 += __shfl_xor_sync(0xffffffffu, sum1, 1);
        sum1 += __shfl_xor_sync(0xffffffffu, sum1, 2);
        L0 = L0 * a0 + sum0;
        L1 = L1 * a1 + sum1;
        M0 = Mn0;
        M1 = Mn1;
#pragma unroll
        for (int ht = 0; ht < 16; ht++) {
            acc[ht][0] *= a0;
            acc[ht][1] *= a0;
            acc[ht][2] *= a1;
            acc[ht][3] *= a1;
        }

        // ---- O += P V (3-pass split; P fragments built from S registers) ----
#pragma unroll
        for (int kk = 0; kk < 4; kk++) {
            const int t0 = kk * 2, t1 = kk * 2 + 1;
            uint32_t aph[4], apl[4];
            aph[0] = pack_hi_lo(c[t0][0], c[t0][1], apl[0]);
            aph[1] = pack_hi_lo(c[t0][2], c[t0][3], apl[1]);
            aph[2] = pack_hi_lo(c[t1][0], c[t1][1], apl[2]);
            aph[3] = pack_hi_lo(c[t1][2], c[t1][3], apl[3]);
#pragma unroll
            for (int hp = 0; hp < 8; hp++) {
                uint32_t vh4[4], vl4[4];
                const int row = hp * 16 + lr + (lg >> 1) * 8;
                const int ch = kk * 2 + (lg & 1);
                const uint32_t a = (uint32_t)((row * 8 + (ch ^ (row & 7))) * 16);
                ldsm_x4(vh4[0], vh4[1], vh4[2], vh4[3], sVh + a);
                ldsm_x4(vl4[0], vl4[1], vl4[2], vl4[3], sVl + a);
                mma16816(acc[hp * 2],     aph, &vh4[0]);
                mma16816(acc[hp * 2 + 1], aph, &vh4[2]);
                mma16816(acc[hp * 2],     aph, &vl4[0]);
                mma16816(acc[hp * 2 + 1], aph, &vl4[2]);
                mma16816(acc[hp * 2],     apl, &vh4[0]);
                mma16816(acc[hp * 2 + 1], apl, &vh4[2]);
            }
        }
    }

    const float i0 = 1.0f / L0, i1 = 1.0f / L1;
    const int rowg = m0 + w * 16 + (lane >> 2);
#pragma unroll
    for (int ht = 0; ht < 16; ht++) {
        const int col = n * HD + ht * 8 + (lane & 3) * 2;
        *reinterpret_cast<float2*>(&R[(size_t)rowg * D_EMB + col]) =
            make_float2(acc[ht][0] * i0, acc[ht][1] * i0);
        *reinterpret_cast<float2*>(&R[(size_t)(rowg + 8) * D_EMB + col]) =
            make_float2(acc[ht][2] * i1, acc[ht][3] * i1);
    }
}

// ---------------------------------------------------------------------------
extern "C" void kernel_launch(void* const* d_in, const int* in_sizes, int n_in,
                              void* d_out, int out_size) {
    const float* X  = (const float*)d_in[0];
    const float* Wq = (const float*)d_in[1];
    const float* Wk = (const float*)d_in[2];
    const float* Wv = (const float*)d_in[3];
    const float* Wo = (const float*)d_in[4];
    float* out = (float*)d_out;

    float *qp, *kp, *vp, *rp;
    cudaGetSymbolAddress((void**)&qp, g_Q);
    cudaGetSymbolAddress((void**)&kp, g_K);
    cudaGetSymbolAddress((void**)&vp, g_V);
    cudaGetSymbolAddress((void**)&rp, g_R);
    __nv_bfloat16 *xh, *xl, *rh, *rl;
    __nv_bfloat16 *wqh, *wql, *wkh, *wkl, *wvh, *wvl, *woh, *wol;
    __nv_bfloat16 *qbh, *qbl, *kbh, *kbl, *vth, *vtl;
    cudaGetSymbolAddress((void**)&xh, g_Xh);
    cudaGetSymbolAddress((void**)&xl, g_Xl);
    cudaGetSymbolAddress((void**)&rh, g_Rh);
    cudaGetSymbolAddress((void**)&rl, g_Rl);
    cudaGetSymbolAddress((void**)&wqh, g_Wqh);
    cudaGetSymbolAddress((void**)&wql, g_Wql);
    cudaGetSymbolAddress((void**)&wkh, g_Wkh);
    cudaGetSymbolAddress((void**)&wkl, g_Wkl);
    cudaGetSymbolAddress((void**)&wvh, g_Wvh);
    cudaGetSymbolAddress((void**)&wvl, g_Wvl);
    cudaGetSymbolAddress((void**)&woh, g_Woh);
    cudaGetSymbolAddress((void**)&wol, g_Wol);
    cudaGetSymbolAddress((void**)&qbh, g_Qbh);
    cudaGetSymbolAddress((void**)&qbl, g_Qbl);
    cudaGetSymbolAddress((void**)&kbh, g_Kbh);
    cudaGetSymbolAddress((void**)&kbl, g_Kbl);
    cudaGetSymbolAddress((void**)&vth, g_Vth);
    cudaGetSymbolAddress((void**)&vtl, g_Vtl);

    const int NELE4 = T_SEQ * D_EMB / 4 / 256;

    // input conversions / splits
    convA<<<NELE4, 256>>>(X, xh, xl, 1.0f);
    convW<<<dim3(HD / 32, D_EMB / 32, NHEADS), dim3(32, 8)>>>(Wq, wqh, wql, HD);
    convW<<<dim3(HD / 32, D_EMB / 32, NHEADS), dim3(32, 8)>>>(Wk, wkh, wkl, HD);
    convW<<<dim3(HD / 32, D_EMB / 32, NHEADS), dim3(32, 8)>>>(Wv, wvh, wvl, HD);
    convW<<<dim3(D_EMB / 32, D_EMB / 32, 1), dim3(32, 8)>>>(Wo, woh, wol, D_EMB);

    // HMMA projection GEMMs (fp32 outputs)
    cudaFuncSetAttribute(gemm_mma, cudaFuncAttributeMaxDynamicSharedMemorySize,
                         GEMM_SMEM);
    const dim3 gg(D_EMB / BN, T_SEQ / BM);
    gemm_mma<<<gg, 256, GEMM_SMEM>>>(xh, xl, wqh, wql, qp);
    gemm_mma<<<gg, 256, GEMM_SMEM>>>(xh, xl, wkh, wkl, kp);
    gemm_mma<<<gg, 256, GEMM_SMEM>>>(xh, xl, wvh, wvl, vp);

    // attention operand prep: Q scaled+split, K split, V transposed+split
    convA<<<NELE4, 256>>>(qp, qbh, qbl, 0.08838834764831843f);
    convA<<<NELE4, 256>>>(kp, kbh, kbl, 1.0f);
    convW<<<dim3(D_EMB / 32, T_SEQ / 32, 1), dim3(32, 8)>>>(vp, vth, vtl, D_EMB);

    // HMMA flash attention
    cudaFuncSetAttribute(attn_mma, cudaFuncAttributeMaxDynamicSharedMemorySize,
                         ATTN_SMEM);
    attn_mma<<<dim3(T_SEQ / 64, NHEADS), 128, ATTN_SMEM>>>(qbh, qbl, kbh, kbl,
                                                           vth, vtl, rp);

    // out-projection
    convA<<<NELE4, 256>>>(rp, rh, rl, 1.0f);
    gemm_mma<<<gg, 256, GEMM_SMEM>>>(rh, rl, woh, wol, out);
}

// round 5
// speedup vs baseline: 3.7866x; 1.5353x over previous
#include <cuda_runtime.h>
#include <cuda_bf16.h>
#include <stdint.h>
#include <math.h>

#define T_SEQ 2048
#define D_EMB 2048
#define HD    128
#define NHEADS 16
#define QK_SCALE 0.08838834764831843f

// ---------------- scratch (no allocs allowed) ----------------
__device__ float g_V[T_SEQ * D_EMB];  // fp32 V for transpose kernel

__device__ __nv_bfloat16 g_Xh[T_SEQ * D_EMB], g_Xl[T_SEQ * D_EMB];
__device__ __nv_bfloat16 g_Rh[T_SEQ * D_EMB], g_Rl[T_SEQ * D_EMB];
// transposed weights, [N=out][K=in] K-major, hi/lo split
__device__ __nv_bfloat16 g_Wqh[D_EMB * D_EMB], g_Wql[D_EMB * D_EMB];
__device__ __nv_bfloat16 g_Wkh[D_EMB * D_EMB], g_Wkl[D_EMB * D_EMB];
__device__ __nv_bfloat16 g_Wvh[D_EMB * D_EMB], g_Wvl[D_EMB * D_EMB];
__device__ __nv_bfloat16 g_Woh[D_EMB * D_EMB], g_Wol[D_EMB * D_EMB];
// attention operands: Q/K split (t, n*h); V split transposed [n*h][t]
__device__ __nv_bfloat16 g_Qbh[T_SEQ * D_EMB], g_Qbl[T_SEQ * D_EMB];
__device__ __nv_bfloat16 g_Kbh[T_SEQ * D_EMB], g_Kbl[T_SEQ * D_EMB];
__device__ __nv_bfloat16 g_Vth[D_EMB * T_SEQ], g_Vtl[D_EMB * T_SEQ];

// ---------------- PTX helpers (base sm_103-legal only) ----------------
__device__ __forceinline__ uint32_t smem_u32(const void* p) {
    uint32_t a;
    asm("{ .reg .u64 t; cvta.to.shared.u64 t, %1; cvt.u32.u64 %0, t; }"
        : "=r"(a) : "l"(p));
    return a;
}
#define CP_ASYNC16(dst, src) \
    asm volatile("cp.async.cg.shared.global [%0], [%1], 16;" :: "r"(dst), "l"(src))
#define CP_COMMIT() asm volatile("cp.async.commit_group;" ::: "memory")
#define CP_WAIT(n) asm volatile("cp.async.wait_group %0;" :: "n"(n) : "memory")

__device__ __forceinline__ void ldsm_x4(uint32_t& r0, uint32_t& r1, uint32_t& r2,
                                        uint32_t& r3, uint32_t addr) {
    asm volatile("ldmatrix.sync.aligned.m8n8.x4.shared.b16 {%0,%1,%2,%3}, [%4];"
                 : "=r"(r0), "=r"(r1), "=r"(r2), "=r"(r3) : "r"(addr));
}
__device__ __forceinline__ void mma16816(float* c, const uint32_t* a,
                                         const uint32_t* b) {
    asm volatile(
        "mma.sync.aligned.m16n8k16.row.col.f32.bf16.bf16.f32 "
        "{%0,%1,%2,%3}, {%4,%5,%6,%7}, {%8,%9}, {%0,%1,%2,%3};"
        : "+f"(c[0]), "+f"(c[1]), "+f"(c[2]), "+f"(c[3])
        : "r"(a[0]), "r"(a[1]), "r"(a[2]), "r"(a[3]), "r"(b[0]), "r"(b[1]));
}
__device__ __forceinline__ uint32_t pack_hi_lo(float x, float y, uint32_t& lo) {
    const __nv_bfloat16 hx = __float2bfloat16(x), hy = __float2bfloat16(y);
    const __nv_bfloat16 lx = __float2bfloat16(x - __bfloat162float(hx));
    const __nv_bfloat16 ly = __float2bfloat16(y - __bfloat162float(hy));
    lo = (uint32_t)*(const uint16_t*)&lx | ((uint32_t)*(const uint16_t*)&ly << 16);
    return (uint32_t)*(const uint16_t*)&hx | ((uint32_t)*(const uint16_t*)&hy << 16);
}

// ---------------- conversion kernels ----------------
__global__ __launch_bounds__(256) void convA(const float* __restrict__ A,
                                             __nv_bfloat16* __restrict__ H,
                                             __nv_bfloat16* __restrict__ L,
                                             float scale) {
    const int i = blockIdx.x * 256 + threadIdx.x;
    float4 v = reinterpret_cast<const float4*>(A)[i];
    __nv_bfloat16 h[4], l[4];
    const float x[4] = {v.x * scale, v.y * scale, v.z * scale, v.w * scale};
#pragma unroll
    for (int j = 0; j < 4; j++) {
        h[j] = __float2bfloat16(x[j]);
        l[j] = __float2bfloat16(x[j] - __bfloat162float(h[j]));
    }
    reinterpret_cast<uint2*>(H)[i] = *reinterpret_cast<uint2*>(h);
    reinterpret_cast<uint2*>(L)[i] = *reinterpret_cast<uint2*>(l);
}

// W[(head) n][k][j] -> Bt[n*hd + j][k] hi/lo (also used as plain transposer)
__global__ __launch_bounds__(256) void convW(const float* __restrict__ W,
                                             __nv_bfloat16* __restrict__ H,
                                             __nv_bfloat16* __restrict__ L, int hd) {
    __shared__ float t[32][33];
    const int n = blockIdx.z;
    const int j0 = blockIdx.x * 32, k0 = blockIdx.y * 32;
    const int tx = threadIdx.x, ty = threadIdx.y;
    const float* Wn = W + (size_t)n * D_EMB * hd;
#pragma unroll
    for (int y = ty; y < 32; y += 8) t[y][tx] = Wn[(size_t)(k0 + y) * hd + j0 + tx];
    __syncthreads();
#pragma unroll
    for (int y = ty; y < 32; y += 8) {
        const float v = t[tx][y];
        const __nv_bfloat16 h = __float2bfloat16(v);
        const __nv_bfloat16 l = __float2bfloat16(v - __bfloat162float(h));
        const size_t o = (size_t)(n * hd + j0 + y) * D_EMB + k0 + tx;
        H[o] = h;
        L[o] = l;
    }
}

// ---------------- split-bf16 HMMA GEMM core ----------------
#define BM 128
#define BN 128
#define BK 32
#define GEMM_SMEM 65536

__device__ __forceinline__ uint32_t swz(uint32_t base, int row, int chunk) {
    return base + (((row << 2) + (chunk ^ ((row >> 1) & 3))) << 4);
}

__device__ __forceinline__ void stage_tile(uint32_t sbase,
                                           const __nv_bfloat16* __restrict__ g,
                                           int row0, int k0, int tid) {
#pragma unroll
    for (int u = tid; u < 512; u += 256) {
        const int row = u >> 2, ch = u & 3;
        const uint32_t dst = swz(sbase, row, ch);
        const __nv_bfloat16* src = g + (size_t)(row0 + row) * D_EMB + k0 + ch * 8;
        CP_ASYNC16(dst, src);
    }
}

// mainloop producing acc[2][8][4] for CTA tile (bm, bn)
__device__ __forceinline__ void gemm_core(
    uint32_t sb, const __nv_bfloat16* Ah, const __nv_bfloat16* Al,
    const __nv_bfloat16* Bh, const __nv_bfloat16* Bl, int bm, int bn, int tid,
    float acc[2][8][4]) {
    const int lane = tid & 31;
    const int wid = tid >> 5;
    const int wm = wid & 3;
    const int wn = wid >> 2;
    const int lr = lane & 7;
    const int lg = lane >> 3;

#pragma unroll
    for (int mt = 0; mt < 2; mt++)
#pragma unroll
        for (int nt = 0; nt < 8; nt++)
#pragma unroll
            for (int e = 0; e < 4; e++) acc[mt][nt][e] = 0.0f;

    stage_tile(sb + 0,     Ah, bm, 0, tid);
    stage_tile(sb + 8192,  Al, bm, 0, tid);
    stage_tile(sb + 16384, Bh, bn, 0, tid);
    stage_tile(sb + 24576, Bl, bn, 0, tid);
    CP_COMMIT();

    const int NITER = D_EMB / BK;
    for (int c = 0; c < NITER; c++) {
        const int b = c & 1;
        if (c + 1 < NITER) {
            const uint32_t s1 = sb + (b ^ 1) * 32768;
            const int k0 = (c + 1) * BK;
            stage_tile(s1 + 0,     Ah, bm, k0, tid);
            stage_tile(s1 + 8192,  Al, bm, k0, tid);
            stage_tile(s1 + 16384, Bh, bn, k0, tid);
            stage_tile(s1 + 24576, Bl, bn, k0, tid);
            CP_COMMIT();
            CP_WAIT(1);
        } else {
            CP_WAIT(0);
        }
        __syncthreads();

        const uint32_t sAh = sb + b * 32768;
        const uint32_t sAl = sAh + 8192;
        const uint32_t sBh = sAh + 16384;
        const uint32_t sBl = sAh + 24576;

#pragma unroll
        for (int kk = 0; kk < 2; kk++) {
            uint32_t ah[2][4], al[2][4];
#pragma unroll
            for (int mt = 0; mt < 2; mt++) {
                const int row = wm * 32 + mt * 16 + lr + (lg & 1) * 8;
                const int ch = kk * 2 + (lg >> 1);
                ldsm_x4(ah[mt][0], ah[mt][1], ah[mt][2], ah[mt][3],
                        swz(sAh, row, ch));
                ldsm_x4(al[mt][0], al[mt][1], al[mt][2], al[mt][3],
                        swz(sAl, row, ch));
            }
            uint32_t bh[8][2], bl[8][2];
#pragma unroll
            for (int np = 0; np < 4; np++) {
                const int row = wn * 64 + np * 16 + lr + (lg >> 1) * 8;
                const int ch = kk * 2 + (lg & 1);
                ldsm_x4(bh[np * 2][0], bh[np * 2][1], bh[np * 2 + 1][0],
                        bh[np * 2 + 1][1], swz(sBh, row, ch));
                ldsm_x4(bl[np * 2][0], bl[np * 2][1], bl[np * 2 + 1][0],
                        bl[np * 2 + 1][1], swz(sBl, row, ch));
            }
#pragma unroll
            for (int mt = 0; mt < 2; mt++)
#pragma unroll
                for (int nt = 0; nt < 8; nt++) {
                    mma16816(acc[mt][nt], ah[mt], bh[nt]);
                    mma16816(acc[mt][nt], ah[mt], bl[nt]);
                    mma16816(acc[mt][nt], al[mt], bh[nt]);
                }
        }
        __syncthreads();
    }
}

// fused QKV: z=0 -> Q scaled+split; z=1 -> K split; z=2 -> V fp32
__global__ __launch_bounds__(256, 1) void gemm_qkv(
    const __nv_bfloat16* __restrict__ Xh, const __nv_bfloat16* __restrict__ Xl,
    const __nv_bfloat16* __restrict__ Wqh, const __nv_bfloat16* __restrict__ Wql,
    const __nv_bfloat16* __restrict__ Wkh, const __nv_bfloat16* __restrict__ Wkl,
    const __nv_bfloat16* __restrict__ Wvh, const __nv_bfloat16* __restrict__ Wvl,
    __nv_bfloat16* __restrict__ Qh, __nv_bfloat16* __restrict__ Ql,
    __nv_bfloat16* __restrict__ Kh, __nv_bfloat16* __restrict__ Kl,
    float* __restrict__ V) {
    extern __shared__ char sm[];
    const uint32_t sb = smem_u32(sm);
    const int tid = threadIdx.x;
    const int lane = tid & 31;
    const int wid = tid >> 5;
    const int z = blockIdx.z;
    const int bm = blockIdx.y * BM;
    const int bn = blockIdx.x * BN;

    const __nv_bfloat16* Bh = (z == 0) ? Wqh : (z == 1) ? Wkh : Wvh;
    const __nv_bfloat16* Bl = (z == 0) ? Wql : (z == 1) ? Wkl : Wvl;

    float acc[2][8][4];
    gemm_core(sb, Xh, Xl, Bh, Bl, bm, bn, tid, acc);

    const int wm = wid & 3;
    const int wn = wid >> 2;
    if (z == 2) {
#pragma unroll
        for (int mt = 0; mt < 2; mt++) {
            const int row = bm + wm * 32 + mt * 16 + (lane >> 2);
#pragma unroll
            for (int nt = 0; nt < 8; nt++) {
                const int col = bn + wn * 64 + nt * 8 + (lane & 3) * 2;
                *reinterpret_cast<float2*>(&V[(size_t)row * D_EMB + col]) =
                    make_float2(acc[mt][nt][0], acc[mt][nt][1]);
                *reinterpret_cast<float2*>(&V[(size_t)(row + 8) * D_EMB + col]) =
                    make_float2(acc[mt][nt][2], acc[mt][nt][3]);
            }
        }
    } else {
        __nv_bfloat16* H = (z == 0) ? Qh : Kh;
        __nv_bfloat16* L = (z == 0) ? Ql : Kl;
        const float s = (z == 0) ? QK_SCALE : 1.0f;
#pragma unroll
        for (int mt = 0; mt < 2; mt++) {
            const int row = bm + wm * 32 + mt * 16 + (lane >> 2);
#pragma unroll
            for (int nt = 0; nt < 8; nt++) {
                const int col = bn + wn * 64 + nt * 8 + (lane & 3) * 2;
                uint32_t lo0, lo1;
                const uint32_t hi0 =
                    pack_hi_lo(acc[mt][nt][0] * s, acc[mt][nt][1] * s, lo0);
                const uint32_t hi1 =
                    pack_hi_lo(acc[mt][nt][2] * s, acc[mt][nt][3] * s, lo1);
                *reinterpret_cast<uint32_t*>(&H[(size_t)row * D_EMB + col]) = hi0;
                *reinterpret_cast<uint32_t*>(&L[(size_t)row * D_EMB + col]) = lo0;
                *reinterpret_cast<uint32_t*>(&H[(size_t)(row + 8) * D_EMB + col]) = hi1;
                *reinterpret_cast<uint32_t*>(&L[(size_t)(row + 8) * D_EMB + col]) = lo1;
            }
        }
    }
}

// out-projection: fp32 output
__global__ __launch_bounds__(256, 1) void gemm_out(
    const __nv_bfloat16* __restrict__ Ah, const __nv_bfloat16* __restrict__ Al,
    const __nv_bfloat16* __restrict__ Bh, const __nv_bfloat16* __restrict__ Bl,
    float* __restrict__ C) {
    extern __shared__ char sm[];
    const uint32_t sb = smem_u32(sm);
    const int tid = threadIdx.x;
    const int lane = tid & 31;
    const int wid = tid >> 5;
    const int bm = blockIdx.y * BM;
    const int bn = blockIdx.x * BN;

    float acc[2][8][4];
    gemm_core(sb, Ah, Al, Bh, Bl, bm, bn, tid, acc);

    const int wm = wid & 3;
    const int wn = wid >> 2;
#pragma unroll
    for (int mt = 0; mt < 2; mt++) {
        const int row = bm + wm * 32 + mt * 16 + (lane >> 2);
#pragma unroll
        for (int nt = 0; nt < 8; nt++) {
            const int col = bn + wn * 64 + nt * 8 + (lane & 3) * 2;
            *reinterpret_cast<float2*>(&C[(size_t)row * D_EMB + col]) =
                make_float2(acc[mt][nt][0], acc[mt][nt][1]);
            *reinterpret_cast<float2*>(&C[(size_t)(row + 8) * D_EMB + col]) =
                make_float2(acc[mt][nt][2], acc[mt][nt][3]);
        }
    }
}

// ---------------- HMMA flash attention (pipelined loads) ----------------
#define ATTN_SMEM 98304

__global__ __launch_bounds__(128, 2) void attn_mma(
    const __nv_bfloat16* __restrict__ Qh, const __nv_bfloat16* __restrict__ Ql,
    const __nv_bfloat16* __restrict__ Kh, const __nv_bfloat16* __restrict__ Kl,
    const __nv_bfloat16* __restrict__ Vth, const __nv_bfloat16* __restrict__ Vtl,
    __nv_bfloat16* __restrict__ Rh, __nv_bfloat16* __restrict__ Rl) {
    extern __shared__ char sm[];
    const uint32_t sb = smem_u32(sm);
    const uint32_t sQh = sb, sQl = sb + 16384;
    const uint32_t sKh = sb + 32768, sKl = sb + 49152;
    const uint32_t sVh = sb + 65536, sVl = sb + 81920;

    const int n = blockIdx.y;
    const int m0 = blockIdx.x * 64;
    const int tid = threadIdx.x;
    const int lane = tid & 31;
    const int w = tid >> 5;
    const int lr = lane & 7;
    const int lg = lane >> 3;

    // group 1: Q (hi+lo)
    for (int u = tid; u < 1024; u += 128) {
        const int row = u >> 4, ch = u & 15;
        const uint32_t d = (uint32_t)((row * 16 + (ch ^ (row & 7))) * 16);
        const size_t g = (size_t)(m0 + row) * D_EMB + n * HD + ch * 8;
        CP_ASYNC16(sQh + d, Qh + g);
        CP_ASYNC16(sQl + d, Ql + g);
    }
    CP_COMMIT();
    // group 2: K(0)
    for (int u = tid; u < 1024; u += 128) {
        const int row = u >> 4, ch = u & 15;
        const uint32_t d = (uint32_t)((row * 16 + (ch ^ (row & 7))) * 16);
        const size_t g = (size_t)row * D_EMB + n * HD + ch * 8;
        CP_ASYNC16(sKh + d, Kh + g);
        CP_ASYNC16(sKl + d, Kl + g);
    }
    CP_COMMIT();
    // group 3: V(0)
    for (int u = tid; u < 1024; u += 128) {
        const int row = u >> 3, ch = u & 7;
        const uint32_t d = (uint32_t)((row * 8 + (ch ^ (row & 7))) * 16);
        const size_t g = (size_t)(n * HD + row) * T_SEQ + ch * 8;
        CP_ASYNC16(sVh + d, Vth + g);
        CP_ASYNC16(sVl + d, Vtl + g);
    }
    CP_COMMIT();

    float acc[16][4];
#pragma unroll
    for (int ht = 0; ht < 16; ht++)
#pragma unroll
        for (int e = 0; e < 4; e++) acc[ht][e] = 0.0f;
    float M0 = -1e30f, M1 = -1e30f, L0 = 0.0f, L1 = 0.0f;

    const int NT = T_SEQ / 64;
    for (int it = 0; it < NT; it++) {
        // K(it) ready (groups complete in order; only newest may pend)
        CP_WAIT(1);
        __syncthreads();

        // ---- S = Q K^T (3-pass split) ----
        float c[8][4];
#pragma unroll
        for (int t = 0; t < 8; t++)
#pragma unroll
            for (int e = 0; e < 4; e++) c[t][e] = 0.0f;

#pragma unroll
        for (int kk = 0; kk < 8; kk++) {
            uint32_t qh4[4], ql4[4];
            {
                const int row = w * 16 + lr + (lg & 1) * 8;
                const int ch = kk * 2 + (lg >> 1);
                const uint32_t a = (uint32_t)((row * 16 + (ch ^ (row & 7))) * 16);
                ldsm_x4(qh4[0], qh4[1], qh4[2], qh4[3], sQh + a);
                ldsm_x4(ql4[0], ql4[1], ql4[2], ql4[3], sQl + a);
            }
#pragma unroll
            for (int np = 0; np < 4; np++) {
                uint32_t kh4[4], kl4[4];
                const int row = np * 16 + lr + (lg >> 1) * 8;
                const int ch = kk * 2 + (lg & 1);
                const uint32_t a = (uint32_t)((row * 16 + (ch ^ (row & 7))) * 16);
                ldsm_x4(kh4[0], kh4[1], kh4[2], kh4[3], sKh + a);
                ldsm_x4(kl4[0], kl4[1], kl4[2], kl4[3], sKl + a);
                mma16816(c[np * 2],     qh4, &kh4[0]);
                mma16816(c[np * 2 + 1], qh4, &kh4[2]);
                mma16816(c[np * 2],     qh4, &kl4[0]);
                mma16816(c[np * 2 + 1], qh4, &kl4[2]);
                mma16816(c[np * 2],     ql4, &kh4[0]);
                mma16816(c[np * 2 + 1], ql4, &kh4[2]);
            }
        }
        __syncthreads();  // all warps done reading K tile

        // prefetch K(it+1) — overlaps softmax and PV
        if (it + 1 < NT) {
            for (int u = tid; u < 1024; u += 128) {
                const int row = u >> 4, ch = u & 15;
                const uint32_t d = (uint32_t)((row * 16 + (ch ^ (row & 7))) * 16);
                const size_t g =
                    (size_t)((it + 1) * 64 + row) * D_EMB + n * HD + ch * 8;
                CP_ASYNC16(sKh + d, Kh + g);
                CP_ASYNC16(sKl + d, Kl + g);
            }
            CP_COMMIT();
        }

        // ---- online softmax ----
        float mx0 = -1e30f, mx1 = -1e30f;
#pragma unroll
        for (int t = 0; t < 8; t++) {
            mx0 = fmaxf(mx0, fmaxf(c[t][0], c[t][1]));
            mx1 = fmaxf(mx1, fmaxf(c[t][2], c[t][3]));
        }
        mx0 = fmaxf(mx0, __shfl_xor_sync(0xffffffffu, mx0, 1));
        mx0 = fmaxf(mx0, __shfl_xor_sync(0xffffffffu, mx0, 2));
        mx1 = fmaxf(mx1, __shfl_xor_sync(0xffffffffu, mx1, 1));
        mx1 = fmaxf(mx1, __shfl_xor_sync(0xffffffffu, mx1, 2));

        const float Mn0 = fmaxf(M0, mx0), Mn1 = fmaxf(M1, mx1);
        const float a0 = __expf(M0 - Mn0), a1 = __expf(M1 - Mn1);
        float sum0 = 0.0f, sum1 = 0.0f;
#pragma unroll
        for (int t = 0; t < 8; t++) {
            c[t][0] = __expf(c[t][0] - Mn0);
            c[t][1] = __expf(c[t][1] - Mn0);
            c[t][2] = __expf(c[t][2] - Mn1);
            c[t][3] = __expf(c[t][3] - Mn1);
            sum0 += c[t][0] + c[t][1];
            sum1 += c[t][2] + c[t][3];
        }
        sum0 += __shfl_xor_sync(0xffffffffu, sum0, 1);
        sum0 += __shfl_xor_sync(0xffffffffu, sum0, 2);
        sum1 += __shfl_xor_sync(0xffffffffu, sum1, 1);
        sum1 += __shfl_xor_sync(0xffffffffu, sum1, 2);
        L0 = L0 * a0 + sum0;
        L1 = L1 * a1 + sum1;
        M0 = Mn0;
        M1 = Mn1;
#pragma unroll
        for (int ht = 0; ht < 16; ht++) {
            acc[ht][0] *= a0;
            acc[ht][1] *= a0;
            acc[ht][2] *= a1;
            acc[ht][3] *= a1;
        }

        // V(it) ready (only newest group — K(it+1) — may pend)
        if (it + 1 < NT) {
            CP_WAIT(1);
        } else {
            CP_WAIT(0);
        }
        __syncthreads();

        // ---- O += P V (3-pass split) ----
#pragma unroll
        for (int kk = 0; kk < 4; kk++) {
            const int t0 = kk * 2, t1 = kk * 2 + 1;
            uint32_t aph[4], apl[4];
            aph[0] = pack_hi_lo(c[t0][0], c[t0][1], apl[0]);
            aph[1] = pack_hi_lo(c[t0][2], c[t0][3], apl[1]);
            aph[2] = pack_hi_lo(c[t1][0], c[t1][1], apl[2]);
            aph[3] = pack_hi_lo(c[t1][2], c[t1][3], apl[3]);
#pragma unroll
            for (int hp = 0; hp < 8; hp++) {
                uint32_t vh4[4], vl4[4];
                const int row = hp * 16 + lr + (lg >> 1) * 8;
                const int ch = kk * 2 + (lg & 1);
                const uint32_t a = (uint32_t)((row * 8 + (ch ^ (row & 7))) * 16);
                ldsm_x4(vh4[0], vh4[1], vh4[2], vh4[3], sVh + a);
                ldsm_x4(vl4[0], vl4[1], vl4[2], vl4[3], sVl + a);
                mma16816(acc[hp * 2],     aph, &vh4[0]);
                mma16816(acc[hp * 2 + 1], aph, &vh4[2]);
                mma16816(acc[hp * 2],     aph, &vl4[0]);
                mma16816(acc[hp * 2 + 1], aph, &vl4[2]);
                mma16816(acc[hp * 2],     apl, &vh4[0]);
                mma16816(acc[hp * 2 + 1], apl, &vh4[2]);
            }
        }
        __syncthreads();  // all warps done reading V tile

        // prefetch V(it+1)
        if (it + 1 < NT) {
            for (int u = tid; u < 1024; u += 128) {
                const int row = u >> 3, ch = u & 7;
                const uint32_t d = (uint32_t)((row * 8 + (ch ^ (row & 7))) * 16);
                const size_t g =
                    (size_t)(n * HD + row) * T_SEQ + (it + 1) * 64 + ch * 8;
                CP_ASYNC16(sVh + d, Vth + g);
                CP_ASYNC16(sVl + d, Vtl + g);
            }
            CP_COMMIT();
        }
    }

    const float i0 = 1.0f / L0, i1 = 1.0f / L1;
    const int rowg = m0 + w * 16 + (lane >> 2);
#pragma unroll
    for (int ht = 0; ht < 16; ht++) {
        const int col = n * HD + ht * 8 + (lane & 3) * 2;
        uint32_t lo0, lo1;
        const uint32_t hi0 = pack_hi_lo(acc[ht][0] * i0, acc[ht][1] * i0, lo0);
        const uint32_t hi1 = pack_hi_lo(acc[ht][2] * i1, acc[ht][3] * i1, lo1);
        *reinterpret_cast<uint32_t*>(&Rh[(size_t)rowg * D_EMB + col]) = hi0;
        *reinterpret_cast<uint32_t*>(&Rl[(size_t)rowg * D_EMB + col]) = lo0;
        *reinterpret_cast<uint32_t*>(&Rh[(size_t)(rowg + 8) * D_EMB + col]) = hi1;
        *reinterpret_cast<uint32_t*>(&Rl[(size_t)(rowg + 8) * D_EMB + col]) = lo1;
    }
}

// ---------------------------------------------------------------------------
extern "C" void kernel_launch(void* const* d_in, const int* in_sizes, int n_in,
                              void* d_out, int out_size) {
    const float* X  = (const float*)d_in[0];
    const float* Wq = (const float*)d_in[1];
    const float* Wk = (const float*)d_in[2];
    const float* Wv = (const float*)d_in[3];
    const float* Wo = (const float*)d_in[4];
    float* out = (float*)d_out;

    float* vp;
    cudaGetSymbolAddress((void**)&vp, g_V);
    __nv_bfloat16 *xh, *xl, *rh, *rl;
    __nv_bfloat16 *wqh, *wql, *wkh, *wkl, *wvh, *wvl, *woh, *wol;
    __nv_bfloat16 *qbh, *qbl, *kbh, *kbl, *vth, *vtl;
    cudaGetSymbolAddress((void**)&xh, g_Xh);
    cudaGetSymbolAddress((void**)&xl, g_Xl);
    cudaGetSymbolAddress((void**)&rh, g_Rh);
    cudaGetSymbolAddress((void**)&rl, g_Rl);
    cudaGetSymbolAddress((void**)&wqh, g_Wqh);
    cudaGetSymbolAddress((void**)&wql, g_Wql);
    cudaGetSymbolAddress((void**)&wkh, g_Wkh);
    cudaGetSymbolAddress((void**)&wkl, g_Wkl);
    cudaGetSymbolAddress((void**)&wvh, g_Wvh);
    cudaGetSymbolAddress((void**)&wvl, g_Wvl);
    cudaGetSymbolAddress((void**)&woh, g_Woh);
    cudaGetSymbolAddress((void**)&wol, g_Wol);
    cudaGetSymbolAddress((void**)&qbh, g_Qbh);
    cudaGetSymbolAddress((void**)&qbl, g_Qbl);
    cudaGetSymbolAddress((void**)&kbh, g_Kbh);
    cudaGetSymbolAddress((void**)&kbl, g_Kbl);
    cudaGetSymbolAddress((void**)&vth, g_Vth);
    cudaGetSymbolAddress((void**)&vtl, g_Vtl);

    const int NELE4 = T_SEQ * D_EMB / 4 / 256;

    // input conversions / splits
    convA<<<NELE4, 256>>>(X, xh, xl, 1.0f);
    convW<<<dim3(HD / 32, D_EMB / 32, NHEADS), dim3(32, 8)>>>(Wq, wqh, wql, HD);
    convW<<<dim3(HD / 32, D_EMB / 32, NHEADS), dim3(32, 8)>>>(Wk, wkh, wkl, HD);
    convW<<<dim3(HD / 32, D_EMB / 32, NHEADS), dim3(32, 8)>>>(Wv, wvh, wvl, HD);
    convW<<<dim3(D_EMB / 32, D_EMB / 32, 1), dim3(32, 8)>>>(Wo, woh, wol, D_EMB);

    // fused QKV projection (epilogue splits Q/K, V fp32)
    cudaFuncSetAttribute(gemm_qkv, cudaFuncAttributeMaxDynamicSharedMemorySize,
                         GEMM_SMEM);
    cudaFuncSetAttribute(gemm_out, cudaFuncAttributeMaxDynamicSharedMemorySize,
                         GEMM_SMEM);
    gemm_qkv<<<dim3(D_EMB / BN, T_SEQ / BM, 3), 256, GEMM_SMEM>>>(
        xh, xl, wqh, wql, wkh, wkl, wvh, wvl, qbh, qbl, kbh, kbl, vp);

    // V transpose+split
    convW<<<dim3(D_EMB / 32, T_SEQ / 32, 1), dim3(32, 8)>>>(vp, vth, vtl, D_EMB);

    // pipelined HMMA flash attention (writes split R)
    cudaFuncSetAttribute(attn_mma, cudaFuncAttributeMaxDynamicSharedMemorySize,
                         ATTN_SMEM);
    attn_mma<<<dim3(T_SEQ / 64, NHEADS), 128, ATTN_SMEM>>>(qbh, qbl, kbh, kbl,
                                                           vth, vtl, rh, rl);

    // out-projection
    gemm_out<<<dim3(D_EMB / BN, T_SEQ / BM), 256, GEMM_SMEM>>>(rh, rl, woh, wol,
                                                               out);
}

// round 6
// speedup vs baseline: 5.4651x; 1.4433x over previous
#include <cuda_runtime.h>
#include <cuda_fp16.h>
#include <stdint.h>
#include <math.h>

#define T_SEQ 2048
#define D_EMB 2048
#define HD    128
#define NHEADS 16
#define QK_SCALE 0.08838834764831843f
#define WSCALE 256.0f
#define INV_WSCALE (1.0f / 256.0f)

// ---------------- scratch (no allocs allowed) ----------------
__device__ __half g_Xf[T_SEQ * D_EMB];                      // X fp16
__device__ __half g_Rf[T_SEQ * D_EMB];                      // attention out fp16
// weights transposed [N=out][K=in], x256, fp16 hi/lo
__device__ __half g_Wqh[D_EMB * D_EMB], g_Wql[D_EMB * D_EMB];
__device__ __half g_Wkh[D_EMB * D_EMB], g_Wkl[D_EMB * D_EMB];
__device__ __half g_Wvh[D_EMB * D_EMB], g_Wvl[D_EMB * D_EMB];
__device__ __half g_Woh[D_EMB * D_EMB], g_Wol[D_EMB * D_EMB];
// attention operands
__device__ __half g_Qf[T_SEQ * D_EMB];                      // Q scaled fp16
__device__ __half g_Kbh[T_SEQ * D_EMB], g_Kbl[T_SEQ * D_EMB];  // K split fp16
__device__ __half g_Vf[T_SEQ * D_EMB];                      // V fp16 [t][nh]
__device__ __half g_Vt[D_EMB * T_SEQ];                      // V fp16 [nh][t]

// ---------------- PTX helpers (base sm_103-legal only) ----------------
__device__ __forceinline__ uint32_t smem_u32(const void* p) {
    uint32_t a;
    asm("{ .reg .u64 t; cvta.to.shared.u64 t, %1; cvt.u32.u64 %0, t; }"
        : "=r"(a) : "l"(p));
    return a;
}
#define CP_ASYNC16(dst, src) \
    asm volatile("cp.async.cg.shared.global [%0], [%1], 16;" :: "r"(dst), "l"(src))
#define CP_COMMIT() asm volatile("cp.async.commit_group;" ::: "memory")
#define CP_WAIT(n) asm volatile("cp.async.wait_group %0;" :: "n"(n) : "memory")

__device__ __forceinline__ void ldsm_x4(uint32_t& r0, uint32_t& r1, uint32_t& r2,
                                        uint32_t& r3, uint32_t addr) {
    asm volatile("ldmatrix.sync.aligned.m8n8.x4.shared.b16 {%0,%1,%2,%3}, [%4];"
                 : "=r"(r0), "=r"(r1), "=r"(r2), "=r"(r3) : "r"(addr));
}
__device__ __forceinline__ void mma16816(float* c, const uint32_t* a,
                                         const uint32_t* b) {
    asm volatile(
        "mma.sync.aligned.m16n8k16.row.col.f32.f16.f16.f32 "
        "{%0,%1,%2,%3}, {%4,%5,%6,%7}, {%8,%9}, {%0,%1,%2,%3};"
        : "+f"(c[0]), "+f"(c[1]), "+f"(c[2]), "+f"(c[3])
        : "r"(a[0]), "r"(a[1]), "r"(a[2]), "r"(a[3]), "r"(b[0]), "r"(b[1]));
}
__device__ __forceinline__ uint32_t pack_f16(float x, float y) {
    __half2 h = __floats2half2_rn(x, y);
    return *reinterpret_cast<uint32_t*>(&h);
}
__device__ __forceinline__ uint32_t pack_f16_hilo(float x, float y, uint32_t& lo) {
    const __half hx = __float2half_rn(x), hy = __float2half_rn(y);
    const __half lx = __float2half_rn(x - __half2float(hx));
    const __half ly = __float2half_rn(y - __half2float(hy));
    lo = (uint32_t)*(const uint16_t*)&lx | ((uint32_t)*(const uint16_t*)&ly << 16);
    return (uint32_t)*(const uint16_t*)&hx | ((uint32_t)*(const uint16_t*)&hy << 16);
}

// ---------------- conversion kernels ----------------
__global__ __launch_bounds__(256) void convX(const float* __restrict__ A,
                                             __half* __restrict__ F) {
    const int i = blockIdx.x * 256 + threadIdx.x;
    float4 v = reinterpret_cast<const float4*>(A)[i];
    __half f[4] = {__float2half_rn(v.x), __float2half_rn(v.y),
                   __float2half_rn(v.z), __float2half_rn(v.w)};
    reinterpret_cast<uint2*>(F)[i] = *reinterpret_cast<uint2*>(f);
}

// W[(head) n][k][j] -> Wt[n*hd + j][k], x256, fp16 hi/lo
__global__ __launch_bounds__(256) void convW16(const float* __restrict__ W,
                                               __half* __restrict__ H,
                                               __half* __restrict__ L, int hd) {
    __shared__ float t[32][33];
    const int n = blockIdx.z;
    const int j0 = blockIdx.x * 32, k0 = blockIdx.y * 32;
    const int tx = threadIdx.x, ty = threadIdx.y;
    const float* Wn = W + (size_t)n * D_EMB * hd;
#pragma unroll
    for (int y = ty; y < 32; y += 8) t[y][tx] = Wn[(size_t)(k0 + y) * hd + j0 + tx];
    __syncthreads();
#pragma unroll
    for (int y = ty; y < 32; y += 8) {
        const float v = t[tx][y] * WSCALE;
        const __half h = __float2half_rn(v);
        const __half l = __float2half_rn(v - __half2float(h));
        const size_t o = (size_t)(n * hd + j0 + y) * D_EMB + k0 + tx;
        H[o] = h;
        L[o] = l;
    }
}

// fp16 transpose: Vf [T][D] -> Vt [D][T]
__global__ __launch_bounds__(256) void convT16(const __half* __restrict__ A,
                                               __half* __restrict__ B) {
    __shared__ __half t[32][33];
    const int j0 = blockIdx.x * 32, k0 = blockIdx.y * 32;
    const int tx = threadIdx.x, ty = threadIdx.y;
#pragma unroll
    for (int y = ty; y < 32; y += 8) t[y][tx] = A[(size_t)(k0 + y) * D_EMB + j0 + tx];
    __syncthreads();
#pragma unroll
    for (int y = ty; y < 32; y += 8)
        B[(size_t)(j0 + y) * T_SEQ + k0 + tx] = t[tx][y];
}

// ---------------- 2-pass fp16 HMMA GEMM core ----------------
// C = Af[M,K] @ (Bh+Bl)^T, B stored [N][K] (x256); CTA 128x128x32, 8 warps.
// Stage: [X 8K][Bh 8K][Bl 8K] = 24KB, double buffered.
#define BM 128
#define BN 128
#define BK 32
#define STAGE_B 24576
#define GEMM_SMEM (2 * STAGE_B)

__device__ __forceinline__ uint32_t swz(uint32_t base, int row, int chunk) {
    return base + (((row << 2) + (chunk ^ ((row >> 1) & 3))) << 4);
}

__device__ __forceinline__ void stage_tile(uint32_t sbase,
                                           const __half* __restrict__ g,
                                           int row0, int k0, int tid) {
#pragma unroll
    for (int u = tid; u < 512; u += 256) {
        const int row = u >> 2, ch = u & 3;
        const uint32_t dst = swz(sbase, row, ch);
        const __half* src = g + (size_t)(row0 + row) * D_EMB + k0 + ch * 8;
        CP_ASYNC16(dst, src);
    }
}

__device__ __forceinline__ void gemm_core2(
    uint32_t sb, const __half* Af, const __half* Bh, const __half* Bl,
    int bm, int bn, int tid, float acc[2][8][4]) {
    const int lane = tid & 31;
    const int wid = tid >> 5;
    const int wm = wid & 3;
    const int wn = wid >> 2;
    const int lr = lane & 7;
    const int lg = lane >> 3;

#pragma unroll
    for (int mt = 0; mt < 2; mt++)
#pragma unroll
        for (int nt = 0; nt < 8; nt++)
#pragma unroll
            for (int e = 0; e < 4; e++) acc[mt][nt][e] = 0.0f;

    stage_tile(sb + 0,     Af, bm, 0, tid);
    stage_tile(sb + 8192,  Bh, bn, 0, tid);
    stage_tile(sb + 16384, Bl, bn, 0, tid);
    CP_COMMIT();

    const int NITER = D_EMB / BK;
    for (int c = 0; c < NITER; c++) {
        const int b = c & 1;
        if (c + 1 < NITER) {
            const uint32_t s1 = sb + (b ^ 1) * STAGE_B;
            const int k0 = (c + 1) * BK;
            stage_tile(s1 + 0,     Af, bm, k0, tid);
            stage_tile(s1 + 8192,  Bh, bn, k0, tid);
            stage_tile(s1 + 16384, Bl, bn, k0, tid);
            CP_COMMIT();
            CP_WAIT(1);
        } else {
            CP_WAIT(0);
        }
        __syncthreads();

        const uint32_t sX  = sb + b * STAGE_B;
        const uint32_t sBh = sX + 8192;
        const uint32_t sBl = sX + 16384;

#pragma unroll
        for (int kk = 0; kk < 2; kk++) {
            uint32_t a4[2][4];
#pragma unroll
            for (int mt = 0; mt < 2; mt++) {
                const int row = wm * 32 + mt * 16 + lr + (lg & 1) * 8;
                const int ch = kk * 2 + (lg >> 1);
                ldsm_x4(a4[mt][0], a4[mt][1], a4[mt][2], a4[mt][3],
                        swz(sX, row, ch));
            }
            uint32_t bh[8][2], bl[8][2];
#pragma unroll
            for (int np = 0; np < 4; np++) {
                const int row = wn * 64 + np * 16 + lr + (lg >> 1) * 8;
                const int ch = kk * 2 + (lg & 1);
                ldsm_x4(bh[np * 2][0], bh[np * 2][1], bh[np * 2 + 1][0],
                        bh[np * 2 + 1][1], swz(sBh, row, ch));
                ldsm_x4(bl[np * 2][0], bl[np * 2][1], bl[np * 2 + 1][0],
                        bl[np * 2 + 1][1], swz(sBl, row, ch));
            }
#pragma unroll
            for (int mt = 0; mt < 2; mt++)
#pragma unroll
                for (int nt = 0; nt < 8; nt++) {
                    mma16816(acc[mt][nt], a4[mt], bh[nt]);
                    mma16816(acc[mt][nt], a4[mt], bl[nt]);
                }
        }
        __syncthreads();
    }
}

// fused QKV: z=0 -> Q (scaled, fp16); z=1 -> K (split fp16); z=2 -> V (fp16)
__global__ __launch_bounds__(256, 1) void gemm_qkv(
    const __half* __restrict__ Xf,
    const __half* __restrict__ Wqh, const __half* __restrict__ Wql,
    const __half* __restrict__ Wkh, const __half* __restrict__ Wkl,
    const __half* __restrict__ Wvh, const __half* __restrict__ Wvl,
    __half* __restrict__ Qf, __half* __restrict__ Kh, __half* __restrict__ Kl,
    __half* __restrict__ Vf) {
    extern __shared__ char sm[];
    const uint32_t sb = smem_u32(sm);
    const int tid = threadIdx.x;
    const int lane = tid & 31;
    const int wid = tid >> 5;
    const int z = blockIdx.z;
    const int bm = blockIdx.y * BM;
    const int bn = blockIdx.x * BN;

    const __half* Bh = (z == 0) ? Wqh : (z == 1) ? Wkh : Wvh;
    const __half* Bl = (z == 0) ? Wql : (z == 1) ? Wkl : Wvl;

    float acc[2][8][4];
    gemm_core2(sb, Xf, Bh, Bl, bm, bn, tid, acc);

    const int wm = wid & 3;
    const int wn = wid >> 2;
    if (z == 1) {  // K: split fp16
#pragma unroll
        for (int mt = 0; mt < 2; mt++) {
            const int row = bm + wm * 32 + mt * 16 + (lane >> 2);
#pragma unroll
            for (int nt = 0; nt < 8; nt++) {
                const int col = bn + wn * 64 + nt * 8 + (lane & 3) * 2;
                uint32_t lo0, lo1;
                const uint32_t hi0 = pack_f16_hilo(acc[mt][nt][0] * INV_WSCALE,
                                                   acc[mt][nt][1] * INV_WSCALE, lo0);
                const uint32_t hi1 = pack_f16_hilo(acc[mt][nt][2] * INV_WSCALE,
                                                   acc[mt][nt][3] * INV_WSCALE, lo1);
                *reinterpret_cast<uint32_t*>(&Kh[(size_t)row * D_EMB + col]) = hi0;
                *reinterpret_cast<uint32_t*>(&Kl[(size_t)row * D_EMB + col]) = lo0;
                *reinterpret_cast<uint32_t*>(&Kh[(size_t)(row + 8) * D_EMB + col]) = hi1;
                *reinterpret_cast<uint32_t*>(&Kl[(size_t)(row + 8) * D_EMB + col]) = lo1;
            }
        }
    } else {  // Q or V: single fp16
        __half* Dst = (z == 0) ? Qf : Vf;
        const float s = (z == 0) ? (QK_SCALE * INV_WSCALE) : INV_WSCALE;
#pragma unroll
        for (int mt = 0; mt < 2; mt++) {
            const int row = bm + wm * 32 + mt * 16 + (lane >> 2);
#pragma unroll
            for (int nt = 0; nt < 8; nt++) {
                const int col = bn + wn * 64 + nt * 8 + (lane & 3) * 2;
                *reinterpret_cast<uint32_t*>(&Dst[(size_t)row * D_EMB + col]) =
                    pack_f16(acc[mt][nt][0] * s, acc[mt][nt][1] * s);
                *reinterpret_cast<uint32_t*>(&Dst[(size_t)(row + 8) * D_EMB + col]) =
                    pack_f16(acc[mt][nt][2] * s, acc[mt][nt][3] * s);
            }
        }
    }
}

// out-projection: fp32 output
__global__ __launch_bounds__(256, 1) void gemm_out(
    const __half* __restrict__ Af, const __half* __restrict__ Bh,
    const __half* __restrict__ Bl, float* __restrict__ C) {
    extern __shared__ char sm[];
    const uint32_t sb = smem_u32(sm);
    const int tid = threadIdx.x;
    const int lane = tid & 31;
    const int wid = tid >> 5;
    const int bm = blockIdx.y * BM;
    const int bn = blockIdx.x * BN;

    float acc[2][8][4];
    gemm_core2(sb, Af, Bh, Bl, bm, bn, tid, acc);

    const int wm = wid & 3;
    const int wn = wid >> 2;
#pragma unroll
    for (int mt = 0; mt < 2; mt++) {
        const int row = bm + wm * 32 + mt * 16 + (lane >> 2);
#pragma unroll
        for (int nt = 0; nt < 8; nt++) {
            const int col = bn + wn * 64 + nt * 8 + (lane & 3) * 2;
            *reinterpret_cast<float2*>(&C[(size_t)row * D_EMB + col]) =
                make_float2(acc[mt][nt][0] * INV_WSCALE, acc[mt][nt][1] * INV_WSCALE);
            *reinterpret_cast<float2*>(&C[(size_t)(row + 8) * D_EMB + col]) =
                make_float2(acc[mt][nt][2] * INV_WSCALE, acc[mt][nt][3] * INV_WSCALE);
        }
    }
}

// ---------------- fp16 HMMA flash attention (pipelined) ----------------
// smem: Q 16K | Kh 16K | Kl 16K | V 16K = 64KB; 128 threads, 3 CTAs/SM.
#define ATTN_SMEM 65536

__global__ __launch_bounds__(128, 3) void attn_mma(
    const __half* __restrict__ Qf, const __half* __restrict__ Kh,
    const __half* __restrict__ Kl, const __half* __restrict__ Vt,
    __half* __restrict__ Rf) {
    extern __shared__ char sm[];
    const uint32_t sb = smem_u32(sm);
    const uint32_t sQ = sb;
    const uint32_t sKh = sb + 16384, sKl = sb + 32768;
    const uint32_t sV = sb + 49152;

    const int n = blockIdx.y;
    const int m0 = blockIdx.x * 64;
    const int tid = threadIdx.x;
    const int lane = tid & 31;
    const int w = tid >> 5;
    const int lr = lane & 7;
    const int lg = lane >> 3;

    // group 1: Q
    for (int u = tid; u < 1024; u += 128) {
        const int row = u >> 4, ch = u & 15;
        const uint32_t d = (uint32_t)((row * 16 + (ch ^ (row & 7))) * 16);
        CP_ASYNC16(sQ + d, Qf + (size_t)(m0 + row) * D_EMB + n * HD + ch * 8);
    }
    CP_COMMIT();
    // group 2: K(0) hi+lo
    for (int u = tid; u < 1024; u += 128) {
        const int row = u >> 4, ch = u & 15;
        const uint32_t d = (uint32_t)((row * 16 + (ch ^ (row & 7))) * 16);
        const size_t g = (size_t)row * D_EMB + n * HD + ch * 8;
        CP_ASYNC16(sKh + d, Kh + g);
        CP_ASYNC16(sKl + d, Kl + g);
    }
    CP_COMMIT();
    // group 3: V(0)
    for (int u = tid; u < 1024; u += 128) {
        const int row = u >> 3, ch = u & 7;
        const uint32_t d = (uint32_t)((row * 8 + (ch ^ (row & 7))) * 16);
        CP_ASYNC16(sV + d, Vt + (size_t)(n * HD + row) * T_SEQ + ch * 8);
    }
    CP_COMMIT();

    float acc[16][4];
#pragma unroll
    for (int ht = 0; ht < 16; ht++)
#pragma unroll
        for (int e = 0; e < 4; e++) acc[ht][e] = 0.0f;
    float M0 = -1e30f, M1 = -1e30f, L0 = 0.0f, L1 = 0.0f;

    const int NT = T_SEQ / 64;
    for (int it = 0; it < NT; it++) {
        CP_WAIT(1);  // K(it) ready (V(it) may pend)
        __syncthreads();

        // ---- S = Q K^T (2-pass: Qf x Kh, Qf x Kl) ----
        float c[8][4];
#pragma unroll
        for (int t = 0; t < 8; t++)
#pragma unroll
            for (int e = 0; e < 4; e++) c[t][e] = 0.0f;

#pragma unroll
        for (int kk = 0; kk < 8; kk++) {
            uint32_t q4[4];
            {
                const int row = w * 16 + lr + (lg & 1) * 8;
                const int ch = kk * 2 + (lg >> 1);
                const uint32_t a = (uint32_t)((row * 16 + (ch ^ (row & 7))) * 16);
                ldsm_x4(q4[0], q4[1], q4[2], q4[3], sQ + a);
            }
#pragma unroll
            for (int np = 0; np < 4; np++) {
                uint32_t kh4[4], kl4[4];
                const int row = np * 16 + lr + (lg >> 1) * 8;
                const int ch = kk * 2 + (lg & 1);
                const uint32_t a = (uint32_t)((row * 16 + (ch ^ (row & 7))) * 16);
                ldsm_x4(kh4[0], kh4[1], kh4[2], kh4[3], sKh + a);
                ldsm_x4(kl4[0], kl4[1], kl4[2], kl4[3], sKl + a);
                mma16816(c[np * 2],     q4, &kh4[0]);
                mma16816(c[np * 2 + 1], q4, &kh4[2]);
                mma16816(c[np * 2],     q4, &kl4[0]);
                mma16816(c[np * 2 + 1], q4, &kl4[2]);
            }
        }
        __syncthreads();  // done reading K tile

        // prefetch K(it+1)
        if (it + 1 < NT) {
            for (int u = tid; u < 1024; u += 128) {
                const int row = u >> 4, ch = u & 15;
                const uint32_t d = (uint32_t)((row * 16 + (ch ^ (row & 7))) * 16);
                const size_t g =
                    (size_t)((it + 1) * 64 + row) * D_EMB + n * HD + ch * 8;
                CP_ASYNC16(sKh + d, Kh + g);
                CP_ASYNC16(sKl + d, Kl + g);
            }
            CP_COMMIT();
        }

        // ---- online softmax ----
        float mx0 = -1e30f, mx1 = -1e30f;
#pragma unroll
        for (int t = 0; t < 8; t++) {
            mx0 = fmaxf(mx0, fmaxf(c[t][0], c[t][1]));
            mx1 = fmaxf(mx1, fmaxf(c[t][2], c[t][3]));
        }
        mx0 = fmaxf(mx0, __shfl_xor_sync(0xffffffffu, mx0, 1));
        mx0 = fmaxf(mx0, __shfl_xor_sync(0xffffffffu, mx0, 2));
        mx1 = fmaxf(mx1, __shfl_xor_sync(0xffffffffu, mx1, 1));
        mx1 = fmaxf(mx1, __shfl_xor_sync(0xffffffffu, mx1, 2));

        const float Mn0 = fmaxf(M0, mx0), Mn1 = fmaxf(M1, mx1);
        const float a0 = __expf(M0 - Mn0), a1 = __expf(M1 - Mn1);
        float sum0 = 0.0f, sum1 = 0.0f;
#pragma unroll
        for (int t = 0; t < 8; t++) {
            c[t][0] = __expf(c[t][0] - Mn0);
            c[t][1] = __expf(c[t][1] - Mn0);
            c[t][2] = __expf(c[t][2] - Mn1);
            c[t][3] = __expf(c[t][3] - Mn1);
            sum0 += c[t][0] + c[t][1];
            sum1 += c[t][2] + c[t][3];
        }
        sum0 += __shfl_xor_sync(0xffffffffu, sum0, 1);
        sum0 += __shfl_xor_sync(0xffffffffu, sum0, 2);
        sum1 += __shfl_xor_sync(0xffffffffu, sum1, 1);
        sum1 += __shfl_xor_sync(0xffffffffu, sum1, 2);
        L0 = L0 * a0 + sum0;
        L1 = L1 * a1 + sum1;
        M0 = Mn0;
        M1 = Mn1;
#pragma unroll
        for (int ht = 0; ht < 16; ht++) {
            acc[ht][0] *= a0;
            acc[ht][1] *= a0;
            acc[ht][2] *= a1;
            acc[ht][3] *= a1;
        }

        // V(it) ready
        if (it + 1 < NT) {
            CP_WAIT(1);
        } else {
            CP_WAIT(0);
        }
        __syncthreads();

        // ---- O += P V (1-pass fp16) ----
#pragma unroll
        for (int kk = 0; kk < 4; kk++) {
            const int t0 = kk * 2, t1 = kk * 2 + 1;
            uint32_t ap[4];
            ap[0] = pack_f16(c[t0][0], c[t0][1]);
            ap[1] = pack_f16(c[t0][2], c[t0][3]);
            ap[2] = pack_f16(c[t1][0], c[t1][1]);
            ap[3] = pack_f16(c[t1][2], c[t1][3]);
#pragma unroll
            for (int hp = 0; hp < 8; hp++) {
                uint32_t v4[4];
                const int row = hp * 16 + lr + (lg >> 1) * 8;
                const int ch = kk * 2 + (lg & 1);
                const uint32_t a = (uint32_t)((row * 8 + (ch ^ (row & 7))) * 16);
                ldsm_x4(v4[0], v4[1], v4[2], v4[3], sV + a);
                mma16816(acc[hp * 2],     ap, &v4[0]);
                mma16816(acc[hp * 2 + 1], ap, &v4[2]);
            }
        }
        __syncthreads();  // done reading V tile

        // prefetch V(it+1)
        if (it + 1 < NT) {
            for (int u = tid; u < 1024; u += 128) {
                const int row = u >> 3, ch = u & 7;
                const uint32_t d = (uint32_t)((row * 8 + (ch ^ (row & 7))) * 16);
                const size_t g =
                    (size_t)(n * HD + row) * T_SEQ + (it + 1) * 64 + ch * 8;
                CP_ASYNC16(sV + d, Vt + g);
            }
            CP_COMMIT();
        }
    }

    const float i0 = 1.0f / L0, i1 = 1.0f / L1;
    const int rowg = m0 + w * 16 + (lane >> 2);
#pragma unroll
    for (int ht = 0; ht < 16; ht++) {
        const int col = n * HD + ht * 8 + (lane & 3) * 2;
        *reinterpret_cast<uint32_t*>(&Rf[(size_t)rowg * D_EMB + col]) =
            pack_f16(acc[ht][0] * i0, acc[ht][1] * i0);
        *reinterpret_cast<uint32_t*>(&Rf[(size_t)(rowg + 8) * D_EMB + col]) =
            pack_f16(acc[ht][2] * i1, acc[ht][3] * i1);
    }
}

// ---------------------------------------------------------------------------
extern "C" void kernel_launch(void* const* d_in, const int* in_sizes, int n_in,
                              void* d_out, int out_size) {
    const float* X  = (const float*)d_in[0];
    const float* Wq = (const float*)d_in[1];
    const float* Wk = (const float*)d_in[2];
    const float* Wv = (const float*)d_in[3];
    const float* Wo = (const float*)d_in[4];
    float* out = (float*)d_out;

    __half *xf, *rf, *qf, *kbh, *kbl, *vf, *vt;
    __half *wqh, *wql, *wkh, *wkl, *wvh, *wvl, *woh, *wol;
    cudaGetSymbolAddress((void**)&xf, g_Xf);
    cudaGetSymbolAddress((void**)&rf, g_Rf);
    cudaGetSymbolAddress((void**)&qf, g_Qf);
    cudaGetSymbolAddress((void**)&kbh, g_Kbh);
    cudaGetSymbolAddress((void**)&kbl, g_Kbl);
    cudaGetSymbolAddress((void**)&vf, g_Vf);
    cudaGetSymbolAddress((void**)&vt, g_Vt);
    cudaGetSymbolAddress((void**)&wqh, g_Wqh);
    cudaGetSymbolAddress((void**)&wql, g_Wql);
    cudaGetSymbolAddress((void**)&wkh, g_Wkh);
    cudaGetSymbolAddress((void**)&wkl, g_Wkl);
    cudaGetSymbolAddress((void**)&wvh, g_Wvh);
    cudaGetSymbolAddress((void**)&wvl, g_Wvl);
    cudaGetSymbolAddress((void**)&woh, g_Woh);
    cudaGetSymbolAddress((void**)&wol, g_Wol);

    const int NELE4 = T_SEQ * D_EMB / 4 / 256;

    // conversions
    convX<<<NELE4, 256>>>(X, xf);
    convW16<<<dim3(HD / 32, D_EMB / 32, NHEADS), dim3(32, 8)>>>(Wq, wqh, wql, HD);
    convW16<<<dim3(HD / 32, D_EMB / 32, NHEADS), dim3(32, 8)>>>(Wk, wkh, wkl, HD);
    convW16<<<dim3(HD / 32, D_EMB / 32, NHEADS), dim3(32, 8)>>>(Wv, wvh, wvl, HD);
    convW16<<<dim3(D_EMB / 32, D_EMB / 32, 1), dim3(32, 8)>>>(Wo, woh, wol, D_EMB);

    // fused QKV projection
    cudaFuncSetAttribute(gemm_qkv, cudaFuncAttributeMaxDynamicSharedMemorySize,
                         GEMM_SMEM);
    cudaFuncSetAttribute(gemm_out, cudaFuncAttributeMaxDynamicSharedMemorySize,
                         GEMM_SMEM);
    gemm_qkv<<<dim3(D_EMB / BN, T_SEQ / BM, 3), 256, GEMM_SMEM>>>(
        xf, wqh, wql, wkh, wkl, wvh, wvl, qf, kbh, kbl, vf);

    // V transpose (fp16)
    convT16<<<dim3(D_EMB / 32, T_SEQ / 32), dim3(32, 8)>>>(vf, vt);

    // flash attention
    cudaFuncSetAttribute(attn_mma, cudaFuncAttributeMaxDynamicSharedMemorySize,
                         ATTN_SMEM);
    attn_mma<<<dim3(T_SEQ / 64, NHEADS), 128, ATTN_SMEM>>>(qf, kbh, kbl, vt, rf);

    // out-projection
    gemm_out<<<dim3(D_EMB / BN, T_SEQ / BM), 256, GEMM_SMEM>>>(rf, woh, wol, out);
}

// round 7
// speedup vs baseline: 6.5876x; 1.2054x over previous
#include <cuda_runtime.h>
#include <cuda_fp16.h>
#include <stdint.h>
#include <math.h>

#define T_SEQ 2048
#define D_EMB 2048
#define HD    128
#define NHEADS 16
#define QK_SCALE 0.08838834764831843f
#define WSCALE 256.0f
#define INV_WSCALE (1.0f / 256.0f)

// ---------------- scratch (no allocs allowed) ----------------
__device__ __half g_Xf[T_SEQ * D_EMB];  // X fp16
__device__ __half g_Rf[T_SEQ * D_EMB];  // attention out fp16
// weights transposed [N=out][K=in], x256, fp16 hi/lo
__device__ __half g_Wqh[D_EMB * D_EMB], g_Wql[D_EMB * D_EMB];
__device__ __half g_Wkh[D_EMB * D_EMB], g_Wkl[D_EMB * D_EMB];
__device__ __half g_Wvh[D_EMB * D_EMB], g_Wvl[D_EMB * D_EMB];
__device__ __half g_Woh[D_EMB * D_EMB], g_Wol[D_EMB * D_EMB];
// attention operands (all single fp16)
__device__ __half g_Qf[T_SEQ * D_EMB];  // Q scaled
__device__ __half g_Kf[T_SEQ * D_EMB];  // K
__device__ __half g_Vf[T_SEQ * D_EMB];  // V [t][n*h]

// ---------------- PTX helpers (base sm_103-legal only) ----------------
__device__ __forceinline__ uint32_t smem_u32(const void* p) {
    uint32_t a;
    asm("{ .reg .u64 t; cvta.to.shared.u64 t, %1; cvt.u32.u64 %0, t; }"
        : "=r"(a) : "l"(p));
    return a;
}
#define CP_ASYNC16(dst, src) \
    asm volatile("cp.async.cg.shared.global [%0], [%1], 16;" :: "r"(dst), "l"(src))
#define CP_COMMIT() asm volatile("cp.async.commit_group;" ::: "memory")
#define CP_WAIT(n) asm volatile("cp.async.wait_group %0;" :: "n"(n) : "memory")

__device__ __forceinline__ void ldsm_x4(uint32_t& r0, uint32_t& r1, uint32_t& r2,
                                        uint32_t& r3, uint32_t addr) {
    asm volatile("ldmatrix.sync.aligned.m8n8.x4.shared.b16 {%0,%1,%2,%3}, [%4];"
                 : "=r"(r0), "=r"(r1), "=r"(r2), "=r"(r3) : "r"(addr));
}
__device__ __forceinline__ void ldsm_x4_t(uint32_t& r0, uint32_t& r1, uint32_t& r2,
                                          uint32_t& r3, uint32_t addr) {
    asm volatile(
        "ldmatrix.sync.aligned.m8n8.x4.trans.shared.b16 {%0,%1,%2,%3}, [%4];"
        : "=r"(r0), "=r"(r1), "=r"(r2), "=r"(r3) : "r"(addr));
}
__device__ __forceinline__ void mma16816(float* c, const uint32_t* a,
                                         const uint32_t* b) {
    asm volatile(
        "mma.sync.aligned.m16n8k16.row.col.f32.f16.f16.f32 "
        "{%0,%1,%2,%3}, {%4,%5,%6,%7}, {%8,%9}, {%0,%1,%2,%3};"
        : "+f"(c[0]), "+f"(c[1]), "+f"(c[2]), "+f"(c[3])
        : "r"(a[0]), "r"(a[1]), "r"(a[2]), "r"(a[3]), "r"(b[0]), "r"(b[1]));
}
__device__ __forceinline__ uint32_t pack_f16(float x, float y) {
    __half2 h = __floats2half2_rn(x, y);
    return *reinterpret_cast<uint32_t*>(&h);
}

// ---------------- conversion kernels ----------------
__global__ __launch_bounds__(256) void convX(const float* __restrict__ A,
                                             __half* __restrict__ F) {
    const int i = blockIdx.x * 256 + threadIdx.x;
    float4 v = reinterpret_cast<const float4*>(A)[i];
    __half f[4] = {__float2half_rn(v.x), __float2half_rn(v.y),
                   __float2half_rn(v.z), __float2half_rn(v.w)};
    reinterpret_cast<uint2*>(F)[i] = *reinterpret_cast<uint2*>(f);
}

// W[(head) n][k][j] -> Wt[n*hd + j][k], x256, fp16 hi/lo
__global__ __launch_bounds__(256) void convW16(const float* __restrict__ W,
                                               __half* __restrict__ H,
                                               __half* __restrict__ L, int hd) {
    __shared__ float t[32][33];
    const int n = blockIdx.z;
    const int j0 = blockIdx.x * 32, k0 = blockIdx.y * 32;
    const int tx = threadIdx.x, ty = threadIdx.y;
    const float* Wn = W + (size_t)n * D_EMB * hd;
#pragma unroll
    for (int y = ty; y < 32; y += 8) t[y][tx] = Wn[(size_t)(k0 + y) * hd + j0 + tx];
    __syncthreads();
#pragma unroll
    for (int y = ty; y < 32; y += 8) {
        const float v = t[tx][y] * WSCALE;
        const __half h = __float2half_rn(v);
        const __half l = __float2half_rn(v - __half2float(h));
        const size_t o = (size_t)(n * hd + j0 + y) * D_EMB + k0 + tx;
        H[o] = h;
        L[o] = l;
    }
}

// ---------------- 2-pass fp16 HMMA GEMM core (3-stage pipeline) ----------------
#define BM 128
#define BN 128
#define BK 32
#define STAGE_B 24576
#define GEMM_SMEM (3 * STAGE_B)

__device__ __forceinline__ uint32_t swz(uint32_t base, int row, int chunk) {
    return base + (((row << 2) + (chunk ^ ((row >> 1) & 3))) << 4);
}

__device__ __forceinline__ void stage_tile(uint32_t sbase,
                                           const __half* __restrict__ g,
                                           int row0, int k0, int tid) {
#pragma unroll
    for (int u = tid; u < 512; u += 256) {
        const int row = u >> 2, ch = u & 3;
        const uint32_t dst = swz(sbase, row, ch);
        const __half* src = g + (size_t)(row0 + row) * D_EMB + k0 + ch * 8;
        CP_ASYNC16(dst, src);
    }
}

__device__ __forceinline__ void stage_all(uint32_t sbase, const __half* Af,
                                          const __half* Bh, const __half* Bl,
                                          int bm, int bn, int k0, int tid) {
    stage_tile(sbase + 0,     Af, bm, k0, tid);
    stage_tile(sbase + 8192,  Bh, bn, k0, tid);
    stage_tile(sbase + 16384, Bl, bn, k0, tid);
    CP_COMMIT();
}

__device__ __forceinline__ void gemm_core2(
    uint32_t sb, const __half* Af, const __half* Bh, const __half* Bl,
    int bm, int bn, int tid, float acc[2][8][4]) {
    const int lane = tid & 31;
    const int wid = tid >> 5;
    const int wm = wid & 3;
    const int wn = wid >> 2;
    const int lr = lane & 7;
    const int lg = lane >> 3;

#pragma unroll
    for (int mt = 0; mt < 2; mt++)
#pragma unroll
        for (int nt = 0; nt < 8; nt++)
#pragma unroll
            for (int e = 0; e < 4; e++) acc[mt][nt][e] = 0.0f;

    stage_all(sb + 0 * STAGE_B, Af, Bh, Bl, bm, bn, 0, tid);
    stage_all(sb + 1 * STAGE_B, Af, Bh, Bl, bm, bn, BK, tid);

    const int NITER = D_EMB / BK;  // 64
    for (int c = 0; c < NITER; c++) {
        if (c == NITER - 1) {
            CP_WAIT(0);
        } else {
            CP_WAIT(1);  // outstanding = {c, c+1} -> chunk c resident
        }
        __syncthreads();
        if (c + 2 < NITER)
            stage_all(sb + ((c + 2) % 3) * STAGE_B, Af, Bh, Bl, bm, bn,
                      (c + 2) * BK, tid);

        const uint32_t sX  = sb + (c % 3) * STAGE_B;
        const uint32_t sBh = sX + 8192;
        const uint32_t sBl = sX + 16384;

#pragma unroll
        for (int kk = 0; kk < 2; kk++) {
            uint32_t a4[2][4];
#pragma unroll
            for (int mt = 0; mt < 2; mt++) {
                const int row = wm * 32 + mt * 16 + lr + (lg & 1) * 8;
                const int ch = kk * 2 + (lg >> 1);
                ldsm_x4(a4[mt][0], a4[mt][1], a4[mt][2], a4[mt][3],
                        swz(sX, row, ch));
            }
            uint32_t bh[8][2], bl[8][2];
#pragma unroll
            for (int np = 0; np < 4; np++) {
                const int row = wn * 64 + np * 16 + lr + (lg >> 1) * 8;
                const int ch = kk * 2 + (lg & 1);
                ldsm_x4(bh[np * 2][0], bh[np * 2][1], bh[np * 2 + 1][0],
                        bh[np * 2 + 1][1], swz(sBh, row, ch));
                ldsm_x4(bl[np * 2][0], bl[np * 2][1], bl[np * 2 + 1][0],
                        bl[np * 2 + 1][1], swz(sBl, row, ch));
            }
#pragma unroll
            for (int mt = 0; mt < 2; mt++)
#pragma unroll
                for (int nt = 0; nt < 8; nt++) {
                    mma16816(acc[mt][nt], a4[mt], bh[nt]);
                    mma16816(acc[mt][nt], a4[mt], bl[nt]);
                }
        }
    }
    __syncthreads();
}

// fused QKV: z=0 -> Q (scaled); z=1 -> K; z=2 -> V; all single fp16
__global__ __launch_bounds__(256, 2) void gemm_qkv(
    const __half* __restrict__ Xf,
    const __half* __restrict__ Wqh, const __half* __restrict__ Wql,
    const __half* __restrict__ Wkh, const __half* __restrict__ Wkl,
    const __half* __restrict__ Wvh, const __half* __restrict__ Wvl,
    __half* __restrict__ Qf, __half* __restrict__ Kf, __half* __restrict__ Vf) {
    extern __shared__ char sm[];
    const uint32_t sb = smem_u32(sm);
    const int tid = threadIdx.x;
    const int lane = tid & 31;
    const int wid = tid >> 5;
    const int z = blockIdx.z;
    const int bm = blockIdx.y * BM;
    const int bn = blockIdx.x * BN;

    const __half* Bh = (z == 0) ? Wqh : (z == 1) ? Wkh : Wvh;
    const __half* Bl = (z == 0) ? Wql : (z == 1) ? Wkl : Wvl;

    float acc[2][8][4];
    gemm_core2(sb, Xf, Bh, Bl, bm, bn, tid, acc);

    const int wm = wid & 3;
    const int wn = wid >> 2;
    __half* Dst = (z == 0) ? Qf : (z == 1) ? Kf : Vf;
    const float s = (z == 0) ? (QK_SCALE * INV_WSCALE) : INV_WSCALE;
#pragma unroll
    for (int mt = 0; mt < 2; mt++) {
        const int row = bm + wm * 32 + mt * 16 + (lane >> 2);
#pragma unroll
        for (int nt = 0; nt < 8; nt++) {
            const int col = bn + wn * 64 + nt * 8 + (lane & 3) * 2;
            *reinterpret_cast<uint32_t*>(&Dst[(size_t)row * D_EMB + col]) =
                pack_f16(acc[mt][nt][0] * s, acc[mt][nt][1] * s);
            *reinterpret_cast<uint32_t*>(&Dst[(size_t)(row + 8) * D_EMB + col]) =
                pack_f16(acc[mt][nt][2] * s, acc[mt][nt][3] * s);
        }
    }
}

// out-projection: fp32 output
__global__ __launch_bounds__(256, 2) void gemm_out(
    const __half* __restrict__ Af, const __half* __restrict__ Bh,
    const __half* __restrict__ Bl, float* __restrict__ C) {
    extern __shared__ char sm[];
    const uint32_t sb = smem_u32(sm);
    const int tid = threadIdx.x;
    const int lane = tid & 31;
    const int wid = tid >> 5;
    const int bm = blockIdx.y * BM;
    const int bn = blockIdx.x * BN;

    float acc[2][8][4];
    gemm_core2(sb, Af, Bh, Bl, bm, bn, tid, acc);

    const int wm = wid & 3;
    const int wn = wid >> 2;
#pragma unroll
    for (int mt = 0; mt < 2; mt++) {
        const int row = bm + wm * 32 + mt * 16 + (lane >> 2);
#pragma unroll
        for (int nt = 0; nt < 8; nt++) {
            const int col = bn + wn * 64 + nt * 8 + (lane & 3) * 2;
            *reinterpret_cast<float2*>(&C[(size_t)row * D_EMB + col]) =
                make_float2(acc[mt][nt][0] * INV_WSCALE, acc[mt][nt][1] * INV_WSCALE);
            *reinterpret_cast<float2*>(&C[(size_t)(row + 8) * D_EMB + col]) =
                make_float2(acc[mt][nt][2] * INV_WSCALE, acc[mt][nt][3] * INV_WSCALE);
        }
    }
}

// ---------------- fp16 HMMA flash attention (1-pass S, trans-V) ----------------
// smem: Q 16K | K 16K | V 16K = 48KB; 128 threads, 4 CTAs/SM -> one wave.
#define ATTN_SMEM 49152

__global__ __launch_bounds__(128, 4) void attn_mma(
    const __half* __restrict__ Qf, const __half* __restrict__ Kf,
    const __half* __restrict__ Vf, __half* __restrict__ Rf) {
    extern __shared__ char sm[];
    const uint32_t sb = smem_u32(sm);
    const uint32_t sQ = sb;
    const uint32_t sK = sb + 16384;
    const uint32_t sV = sb + 32768;

    const int n = blockIdx.y;
    const int m0 = blockIdx.x * 64;
    const int tid = threadIdx.x;
    const int lane = tid & 31;
    const int w = tid >> 5;
    const int lr = lane & 7;
    const int lg = lane >> 3;

    // group 1: Q
    for (int u = tid; u < 1024; u += 128) {
        const int row = u >> 4, ch = u & 15;
        const uint32_t d = (uint32_t)((row * 16 + (ch ^ (row & 7))) * 16);
        CP_ASYNC16(sQ + d, Qf + (size_t)(m0 + row) * D_EMB + n * HD + ch * 8);
    }
    CP_COMMIT();
    // group 2: K(0)
    for (int u = tid; u < 1024; u += 128) {
        const int row = u >> 4, ch = u & 15;
        const uint32_t d = (uint32_t)((row * 16 + (ch ^ (row & 7))) * 16);
        CP_ASYNC16(sK + d, Kf + (size_t)row * D_EMB + n * HD + ch * 8);
    }
    CP_COMMIT();
    // group 3: V(0)  [s][h] rows, 256B each
    for (int u = tid; u < 1024; u += 128) {
        const int row = u >> 4, ch = u & 15;
        const uint32_t d = (uint32_t)((row * 16 + (ch ^ (row & 7))) * 16);
        CP_ASYNC16(sV + d, Vf + (size_t)row * D_EMB + n * HD + ch * 8);
    }
    CP_COMMIT();

    float acc[16][4];
#pragma unroll
    for (int ht = 0; ht < 16; ht++)
#pragma unroll
        for (int e = 0; e < 4; e++) acc[ht][e] = 0.0f;
    float M0 = -1e30f, M1 = -1e30f, L0 = 0.0f, L1 = 0.0f;

    const int NT = T_SEQ / 64;
    for (int it = 0; it < NT; it++) {
        CP_WAIT(1);  // K(it) ready (V(it) may pend)
        __syncthreads();

        // ---- S = Q K^T (1-pass fp16) ----
        float c[8][4];
#pragma unroll
        for (int t = 0; t < 8; t++)
#pragma unroll
            for (int e = 0; e < 4; e++) c[t][e] = 0.0f;

#pragma unroll
        for (int kk = 0; kk < 8; kk++) {
            uint32_t q4[4];
            {
                const int row = w * 16 + lr + (lg & 1) * 8;
                const int ch = kk * 2 + (lg >> 1);
                const uint32_t a = (uint32_t)((row * 16 + (ch ^ (row & 7))) * 16);
                ldsm_x4(q4[0], q4[1], q4[2], q4[3], sQ + a);
            }
#pragma unroll
            for (int np = 0; np < 4; np++) {
                uint32_t k4[4];
                const int row = np * 16 + lr + (lg >> 1) * 8;
                const int ch = kk * 2 + (lg & 1);
                const uint32_t a = (uint32_t)((row * 16 + (ch ^ (row & 7))) * 16);
                ldsm_x4(k4[0], k4[1], k4[2], k4[3], sK + a);
                mma16816(c[np * 2],     q4, &k4[0]);
                mma16816(c[np * 2 + 1], q4, &k4[2]);
            }
        }
        __syncthreads();  // done reading K tile

        // prefetch K(it+1)
        if (it + 1 < NT) {
            for (int u = tid; u < 1024; u += 128) {
                const int row = u >> 4, ch = u & 15;
                const uint32_t d = (uint32_t)((row * 16 + (ch ^ (row & 7))) * 16);
                CP_ASYNC16(sK + d, Kf + (size_t)((it + 1) * 64 + row) * D_EMB +
                                       n * HD + ch * 8);
            }
            CP_COMMIT();
        }

        // ---- online softmax ----
        float mx0 = -1e30f, mx1 = -1e30f;
#pragma unroll
        for (int t = 0; t < 8; t++) {
            mx0 = fmaxf(mx0, fmaxf(c[t][0], c[t][1]));
            mx1 = fmaxf(mx1, fmaxf(c[t][2], c[t][3]));
        }
        mx0 = fmaxf(mx0, __shfl_xor_sync(0xffffffffu, mx0, 1));
        mx0 = fmaxf(mx0, __shfl_xor_sync(0xffffffffu, mx0, 2));
        mx1 = fmaxf(mx1, __shfl_xor_sync(0xffffffffu, mx1, 1));
        mx1 = fmaxf(mx1, __shfl_xor_sync(0xffffffffu, mx1, 2));

        const float Mn0 = fmaxf(M0, mx0), Mn1 = fmaxf(M1, mx1);
        const float a0 = __expf(M0 - Mn0), a1 = __expf(M1 - Mn1);
        float sum0 = 0.0f, sum1 = 0.0f;
#pragma unroll
        for (int t = 0; t < 8; t++) {
            c[t][0] = __expf(c[t][0] - Mn0);
            c[t][1] = __expf(c[t][1] - Mn0);
            c[t][2] = __expf(c[t][2] - Mn1);
            c[t][3] = __expf(c[t][3] - Mn1);
            sum0 += c[t][0] + c[t][1];
            sum1 += c[t][2] + c[t][3];
        }
        sum0 += __shfl_xor_sync(0xffffffffu, sum0, 1);
        sum0 += __shfl_xor_sync(0xffffffffu, sum0, 2);
        sum1 += __shfl_xor_sync(0xffffffffu, sum1, 1);
        sum1 += __shfl_xor_sync(0xffffffffu, sum1, 2);
        L0 = L0 * a0 + sum0;
        L1 = L1 * a1 + sum1;
        M0 = Mn0;
        M1 = Mn1;
#pragma unroll
        for (int ht = 0; ht < 16; ht++) {
            acc[ht][0] *= a0;
            acc[ht][1] *= a0;
            acc[ht][2] *= a1;
            acc[ht][3] *= a1;
        }

        // V(it) ready
        if (it + 1 < NT) {
            CP_WAIT(1);
        } else {
            CP_WAIT(0);
        }
        __syncthreads();

        // ---- O += P V (1-pass, trans-loaded V fragments) ----
#pragma unroll
        for (int kk = 0; kk < 4; kk++) {
            const int t0 = kk * 2, t1 = kk * 2 + 1;
            uint32_t ap[4];
            ap[0] = pack_f16(c[t0][0], c[t0][1]);
            ap[1] = pack_f16(c[t0][2], c[t0][3]);
            ap[2] = pack_f16(c[t1][0], c[t1][1]);
            ap[3] = pack_f16(c[t1][2], c[t1][3]);
#pragma unroll
            for (int hq = 0; hq < 8; hq++) {
                uint32_t v4[4];
                // tiles: rows s = kk*16 + (lg&1)*8 + lr; h-chunk = hq*2 + (lg>>1)
                const int row = kk * 16 + (lg & 1) * 8 + lr;
                const int ch = hq * 2 + (lg >> 1);
                const uint32_t a = (uint32_t)((row * 16 + (ch ^ (row & 7))) * 16);
                ldsm_x4_t(v4[0], v4[1], v4[2], v4[3], sV + a);
                mma16816(acc[hq * 2],     ap, &v4[0]);
                mma16816(acc[hq * 2 + 1], ap, &v4[2]);
            }
        }
        __syncthreads();  // done reading V tile

        // prefetch V(it+1)
        if (it + 1 < NT) {
            for (int u = tid; u < 1024; u += 128) {
                const int row = u >> 4, ch = u & 15;
                const uint32_t d = (uint32_t)((row * 16 + (ch ^ (row & 7))) * 16);
                CP_ASYNC16(sV + d, Vf + (size_t)((it + 1) * 64 + row) * D_EMB +
                                       n * HD + ch * 8);
            }
            CP_COMMIT();
        }
    }

    const float i0 = 1.0f / L0, i1 = 1.0f / L1;
    const int rowg = m0 + w * 16 + (lane >> 2);
#pragma unroll
    for (int ht = 0; ht < 16; ht++) {
        const int col = n * HD + ht * 8 + (lane & 3) * 2;
        *reinterpret_cast<uint32_t*>(&Rf[(size_t)rowg * D_EMB + col]) =
            pack_f16(acc[ht][0] * i0, acc[ht][1] * i0);
        *reinterpret_cast<uint32_t*>(&Rf[(size_t)(rowg + 8) * D_EMB + col]) =
            pack_f16(acc[ht][2] * i1, acc[ht][3] * i1);
    }
}

// ---------------------------------------------------------------------------
extern "C" void kernel_launch(void* const* d_in, const int* in_sizes, int n_in,
                              void* d_out, int out_size) {
    const float* X  = (const float*)d_in[0];
    const float* Wq = (const float*)d_in[1];
    const float* Wk = (const float*)d_in[2];
    const float* Wv = (const float*)d_in[3];
    const float* Wo = (const float*)d_in[4];
    float* out = (float*)d_out;

    __half *xf, *rf, *qf, *kf, *vf;
    __half *wqh, *wql, *wkh, *wkl, *wvh, *wvl, *woh, *wol;
    cudaGetSymbolAddress((void**)&xf, g_Xf);
    cudaGetSymbolAddress((void**)&rf, g_Rf);
    cudaGetSymbolAddress((void**)&qf, g_Qf);
    cudaGetSymbolAddress((void**)&kf, g_Kf);
    cudaGetSymbolAddress((void**)&vf, g_Vf);
    cudaGetSymbolAddress((void**)&wqh, g_Wqh);
    cudaGetSymbolAddress((void**)&wql, g_Wql);
    cudaGetSymbolAddress((void**)&wkh, g_Wkh);
    cudaGetSymbolAddress((void**)&wkl, g_Wkl);
    cudaGetSymbolAddress((void**)&wvh, g_Wvh);
    cudaGetSymbolAddress((void**)&wvl, g_Wvl);
    cudaGetSymbolAddress((void**)&woh, g_Woh);
    cudaGetSymbolAddress((void**)&wol, g_Wol);

    const int NELE4 = T_SEQ * D_EMB / 4 / 256;

    // conversions
    convX<<<NELE4, 256>>>(X, xf);
    convW16<<<dim3(HD / 32, D_EMB / 32, NHEADS), dim3(32, 8)>>>(Wq, wqh, wql, HD);
    convW16<<<dim3(HD / 32, D_EMB / 32, NHEADS), dim3(32, 8)>>>(Wk, wkh, wkl, HD);
    convW16<<<dim3(HD / 32, D_EMB / 32, NHEADS), dim3(32, 8)>>>(Wv, wvh, wvl, HD);
    convW16<<<dim3(D_EMB / 32, D_EMB / 32, 1), dim3(32, 8)>>>(Wo, woh, wol, D_EMB);

    // fused QKV projection
    cudaFuncSetAttribute(gemm_qkv, cudaFuncAttributeMaxDynamicSharedMemorySize,
                         GEMM_SMEM);
    cudaFuncSetAttribute(gemm_out, cudaFuncAttributeMaxDynamicSharedMemorySize,
                         GEMM_SMEM);
    gemm_qkv<<<dim3(D_EMB / BN, T_SEQ / BM, 3), 256, GEMM_SMEM>>>(
        xf, wqh, wql, wkh, wkl, wvh, wvl, qf, kf, vf);

    // flash attention (single wave at 4 CTAs/SM)
    cudaFuncSetAttribute(attn_mma, cudaFuncAttributeMaxDynamicSharedMemorySize,
                         ATTN_SMEM);
    attn_mma<<<dim3(T_SEQ / 64, NHEADS), 128, ATTN_SMEM>>>(qf, kf, vf, rf);

    // out-projection
    gemm_out<<<dim3(D_EMB / BN, T_SEQ / BM), 256, GEMM_SMEM>>>(rf, woh, wol, out);
}

// round 8
// speedup vs baseline: 7.0016x; 1.0628x over previous
#include <cuda_runtime.h>
#include <cuda_fp16.h>
#include <stdint.h>
#include <math.h>

#define T_SEQ 2048
#define D_EMB 2048
#define HD    128
#define NHEADS 16
#define QK_SCALE 0.08838834764831843f
#define WSCALE 256.0f
#define INV_WSCALE (1.0f / 256.0f)

// ---------------- scratch (no allocs allowed) ----------------
__device__ __half g_Xf[T_SEQ * D_EMB];
__device__ __half g_Rf[T_SEQ * D_EMB];
__device__ __half g_Wqh[D_EMB * D_EMB], g_Wql[D_EMB * D_EMB];
__device__ __half g_Wkh[D_EMB * D_EMB], g_Wkl[D_EMB * D_EMB];
__device__ __half g_Wvh[D_EMB * D_EMB], g_Wvl[D_EMB * D_EMB];
__device__ __half g_Woh[D_EMB * D_EMB], g_Wol[D_EMB * D_EMB];
__device__ __half g_Qf[T_SEQ * D_EMB];
__device__ __half g_Kf[T_SEQ * D_EMB];
__device__ __half g_Vf[T_SEQ * D_EMB];

// ---------------- PTX helpers (base sm_103-legal only) ----------------
__device__ __forceinline__ uint32_t smem_u32(const void* p) {
    uint32_t a;
    asm("{ .reg .u64 t; cvta.to.shared.u64 t, %1; cvt.u32.u64 %0, t; }"
        : "=r"(a) : "l"(p));
    return a;
}
#define CP_ASYNC16(dst, src) \
    asm volatile("cp.async.cg.shared.global [%0], [%1], 16;" :: "r"(dst), "l"(src))
#define CP_COMMIT() asm volatile("cp.async.commit_group;" ::: "memory")
#define CP_WAIT(n) asm volatile("cp.async.wait_group %0;" :: "n"(n) : "memory")

__device__ __forceinline__ void ldsm_x4(uint32_t& r0, uint32_t& r1, uint32_t& r2,
                                        uint32_t& r3, uint32_t addr) {
    asm volatile("ldmatrix.sync.aligned.m8n8.x4.shared.b16 {%0,%1,%2,%3}, [%4];"
                 : "=r"(r0), "=r"(r1), "=r"(r2), "=r"(r3) : "r"(addr));
}
__device__ __forceinline__ void ldsm_x4_t(uint32_t& r0, uint32_t& r1, uint32_t& r2,
                                          uint32_t& r3, uint32_t addr) {
    asm volatile(
        "ldmatrix.sync.aligned.m8n8.x4.trans.shared.b16 {%0,%1,%2,%3}, [%4];"
        : "=r"(r0), "=r"(r1), "=r"(r2), "=r"(r3) : "r"(addr));
}
__device__ __forceinline__ void mma16816(float* c, const uint32_t* a,
                                         const uint32_t* b) {
    asm volatile(
        "mma.sync.aligned.m16n8k16.row.col.f32.f16.f16.f32 "
        "{%0,%1,%2,%3}, {%4,%5,%6,%7}, {%8,%9}, {%0,%1,%2,%3};"
        : "+f"(c[0]), "+f"(c[1]), "+f"(c[2]), "+f"(c[3])
        : "r"(a[0]), "r"(a[1]), "r"(a[2]), "r"(a[3]), "r"(b[0]), "r"(b[1]));
}
__device__ __forceinline__ uint32_t pack_f16(float x, float y) {
    __half2 h = __floats2half2_rn(x, y);
    return *reinterpret_cast<uint32_t*>(&h);
}

// ---------------- conversion kernels ----------------
__global__ __launch_bounds__(256) void convX(const float* __restrict__ A,
                                             __half* __restrict__ F) {
    const int i = blockIdx.x * 256 + threadIdx.x;
    float4 v = reinterpret_cast<const float4*>(A)[i];
    __half f[4] = {__float2half_rn(v.x), __float2half_rn(v.y),
                   __float2half_rn(v.z), __float2half_rn(v.w)};
    reinterpret_cast<uint2*>(F)[i] = *reinterpret_cast<uint2*>(f);
}

// merged weight conversion: z = 0/1/2 -> Wq/Wk/Wv (16 heads, hd=128);
// z = 3 -> Wo (1 "head", hd=2048). Output transposed [N][K], x256, fp16 hi/lo.
__global__ __launch_bounds__(256) void convW16all(
    const float* __restrict__ Wq, const float* __restrict__ Wk,
    const float* __restrict__ Wv, const float* __restrict__ Wo,
    __half* __restrict__ Hq, __half* __restrict__ Lq,
    __half* __restrict__ Hk, __half* __restrict__ Lk,
    __half* __restrict__ Hv, __half* __restrict__ Lv,
    __half* __restrict__ Ho, __half* __restrict__ Lo) {
    __shared__ float t[32][33];
    const int z = blockIdx.z;
    const float* W = (z == 0) ? Wq : (z == 1) ? Wk : (z == 2) ? Wv : Wo;
    __half* H = (z == 0) ? Hq : (z == 1) ? Hk : (z == 2) ? Hv : Ho;
    __half* L = (z == 0) ? Lq : (z == 1) ? Lk : (z == 2) ? Lv : Lo;
    const int hd = (z == 3) ? D_EMB : HD;
    const int n  = (z == 3) ? 0 : (blockIdx.x >> 2);
    const int j0 = (z == 3) ? (blockIdx.x * 32) : ((blockIdx.x & 3) * 32);
    const int k0 = blockIdx.y * 32;
    const int tx = threadIdx.x, ty = threadIdx.y;
    const float* Wn = W + (size_t)n * D_EMB * hd;
#pragma unroll
    for (int y = ty; y < 32; y += 8) t[y][tx] = Wn[(size_t)(k0 + y) * hd + j0 + tx];
    __syncthreads();
#pragma unroll
    for (int y = ty; y < 32; y += 8) {
        const float v = t[tx][y] * WSCALE;
        const __half h = __float2half_rn(v);
        const __half l = __float2half_rn(v - __half2float(h));
        const size_t o = (size_t)(n * hd + j0 + y) * D_EMB + k0 + tx;
        H[o] = h;
        L[o] = l;
    }
}

// ---------------- 2-pass fp16 HMMA GEMM (warp 64x64, 128 threads) ----------------
#define BM 128
#define BN 128
#define BK 32
#define STAGE_B 24576
#define GEMM_SMEM (3 * STAGE_B)

__device__ __forceinline__ uint32_t swz(uint32_t base, int row, int chunk) {
    return base + (((row << 2) + (chunk ^ ((row >> 1) & 3))) << 4);
}

__device__ __forceinline__ void stage_tile(uint32_t sbase,
                                           const __half* __restrict__ g,
                                           int row0, int k0, int tid) {
#pragma unroll
    for (int u = tid; u < 512; u += 128) {
        const int row = u >> 2, ch = u & 3;
        const uint32_t dst = swz(sbase, row, ch);
        const __half* src = g + (size_t)(row0 + row) * D_EMB + k0 + ch * 8;
        CP_ASYNC16(dst, src);
    }
}

__device__ __forceinline__ void stage_all(uint32_t sbase, const __half* Af,
                                          const __half* Bh, const __half* Bl,
                                          int bm, int bn, int k0, int tid) {
    stage_tile(sbase + 0,     Af, bm, k0, tid);
    stage_tile(sbase + 8192,  Bh, bn, k0, tid);
    stage_tile(sbase + 16384, Bl, bn, k0, tid);
    CP_COMMIT();
}

__device__ __forceinline__ void gemm_core2(
    uint32_t sb, const __half* Af, const __half* Bh, const __half* Bl,
    int bm, int bn, int tid, float acc[4][8][4]) {
    const int lane = tid & 31;
    const int wid = tid >> 5;
    const int wm = wid & 1;   // 2x2 warp grid
    const int wn = wid >> 1;
    const int lr = lane & 7;
    const int lg = lane >> 3;

#pragma unroll
    for (int mt = 0; mt < 4; mt++)
#pragma unroll
        for (int nt = 0; nt < 8; nt++)
#pragma unroll
            for (int e = 0; e < 4; e++) acc[mt][nt][e] = 0.0f;

    stage_all(sb + 0 * STAGE_B, Af, Bh, Bl, bm, bn, 0, tid);
    stage_all(sb + 1 * STAGE_B, Af, Bh, Bl, bm, bn, BK, tid);

    const int NITER = D_EMB / BK;  // 64
    for (int c = 0; c < NITER; c++) {
        if (c == NITER - 1) {
            CP_WAIT(0);
        } else {
            CP_WAIT(1);
        }
        __syncthreads();
        if (c + 2 < NITER)
            stage_all(sb + ((c + 2) % 3) * STAGE_B, Af, Bh, Bl, bm, bn,
                      (c + 2) * BK, tid);

        const uint32_t sX  = sb + (c % 3) * STAGE_B;
        const uint32_t sBh = sX + 8192;
        const uint32_t sBl = sX + 16384;

#pragma unroll
        for (int kk = 0; kk < 2; kk++) {
            uint32_t a4[4][4];
#pragma unroll
            for (int mt = 0; mt < 4; mt++) {
                const int row = wm * 64 + mt * 16 + lr + (lg & 1) * 8;
                const int ch = kk * 2 + (lg >> 1);
                ldsm_x4(a4[mt][0], a4[mt][1], a4[mt][2], a4[mt][3],
                        swz(sX, row, ch));
            }
            uint32_t bh[8][2], bl[8][2];
#pragma unroll
            for (int np = 0; np < 4; np++) {
                const int row = wn * 64 + np * 16 + lr + (lg >> 1) * 8;
                const int ch = kk * 2 + (lg & 1);
                ldsm_x4(bh[np * 2][0], bh[np * 2][1], bh[np * 2 + 1][0],
                        bh[np * 2 + 1][1], swz(sBh, row, ch));
                ldsm_x4(bl[np * 2][0], bl[np * 2][1], bl[np * 2 + 1][0],
                        bl[np * 2 + 1][1], swz(sBl, row, ch));
            }
#pragma unroll
            for (int mt = 0; mt < 4; mt++)
#pragma unroll
                for (int nt = 0; nt < 8; nt++) {
                    mma16816(acc[mt][nt], a4[mt], bh[nt]);
                    mma16816(acc[mt][nt], a4[mt], bl[nt]);
                }
        }
    }
    __syncthreads();
}

// fused QKV: z=0 -> Q (scaled); z=1 -> K; z=2 -> V; all single fp16
__global__ __launch_bounds__(128, 2) void gemm_qkv(
    const __half* __restrict__ Xf,
    const __half* __restrict__ Wqh, const __half* __restrict__ Wql,
    const __half* __restrict__ Wkh, const __half* __restrict__ Wkl,
    const __half* __restrict__ Wvh, const __half* __restrict__ Wvl,
    __half* __restrict__ Qf, __half* __restrict__ Kf, __half* __restrict__ Vf) {
    extern __shared__ char sm[];
    const uint32_t sb = smem_u32(sm);
    const int tid = threadIdx.x;
    const int lane = tid & 31;
    const int wid = tid >> 5;
    const int z = blockIdx.z;
    const int bm = blockIdx.y * BM;
    const int bn = blockIdx.x * BN;

    const __half* Bh = (z == 0) ? Wqh : (z == 1) ? Wkh : Wvh;
    const __half* Bl = (z == 0) ? Wql : (z == 1) ? Wkl : Wvl;

    float acc[4][8][4];
    gemm_core2(sb, Xf, Bh, Bl, bm, bn, tid, acc);

    const int wm = wid & 1;
    const int wn = wid >> 1;
    __half* Dst = (z == 0) ? Qf : (z == 1) ? Kf : Vf;
    const float s = (z == 0) ? (QK_SCALE * INV_WSCALE) : INV_WSCALE;
#pragma unroll
    for (int mt = 0; mt < 4; mt++) {
        const int row = bm + wm * 64 + mt * 16 + (lane >> 2);
#pragma unroll
        for (int nt = 0; nt < 8; nt++) {
            const int col = bn + wn * 64 + nt * 8 + (lane & 3) * 2;
            *reinterpret_cast<uint32_t*>(&Dst[(size_t)row * D_EMB + col]) =
                pack_f16(acc[mt][nt][0] * s, acc[mt][nt][1] * s);
            *reinterpret_cast<uint32_t*>(&Dst[(size_t)(row + 8) * D_EMB + col]) =
                pack_f16(acc[mt][nt][2] * s, acc[mt][nt][3] * s);
        }
    }
}

// out-projection: fp32 output
__global__ __launch_bounds__(128, 2) void gemm_out(
    const __half* __restrict__ Af, const __half* __restrict__ Bh,
    const __half* __restrict__ Bl, float* __restrict__ C) {
    extern __shared__ char sm[];
    const uint32_t sb = smem_u32(sm);
    const int tid = threadIdx.x;
    const int lane = tid & 31;
    const int wid = tid >> 5;
    const int bm = blockIdx.y * BM;
    const int bn = blockIdx.x * BN;

    float acc[4][8][4];
    gemm_core2(sb, Af, Bh, Bl, bm, bn, tid, acc);

    const int wm = wid & 1;
    const int wn = wid >> 1;
#pragma unroll
    for (int mt = 0; mt < 4; mt++) {
        const int row = bm + wm * 64 + mt * 16 + (lane >> 2);
#pragma unroll
        for (int nt = 0; nt < 8; nt++) {
            const int col = bn + wn * 64 + nt * 8 + (lane & 3) * 2;
            *reinterpret_cast<float2*>(&C[(size_t)row * D_EMB + col]) =
                make_float2(acc[mt][nt][0] * INV_WSCALE, acc[mt][nt][1] * INV_WSCALE);
            *reinterpret_cast<float2*>(&C[(size_t)(row + 8) * D_EMB + col]) =
                make_float2(acc[mt][nt][2] * INV_WSCALE, acc[mt][nt][3] * INV_WSCALE);
        }
    }
}

// ---------------- fp16 HMMA flash attention (32 rows/warp) ----------------
// CTA: 128 threads / 4 warps, 128 query rows (warp owns 32). smem: Q 32K | K 16K | V 16K.
#define ATTN_SMEM 65536

__global__ __launch_bounds__(128, 2) void attn_mma(
    const __half* __restrict__ Qf, const __half* __restrict__ Kf,
    const __half* __restrict__ Vf, __half* __restrict__ Rf) {
    extern __shared__ char sm[];
    const uint32_t sb = smem_u32(sm);
    const uint32_t sQ = sb;
    const uint32_t sK = sb + 32768;
    const uint32_t sV = sb + 49152;

    const int n = blockIdx.y;
    const int m0 = blockIdx.x * 128;
    const int tid = threadIdx.x;
    const int lane = tid & 31;
    const int w = tid >> 5;
    const int lr = lane & 7;
    const int lg = lane >> 3;

    // group 1: Q (128 rows x 256B)
    for (int u = tid; u < 2048; u += 128) {
        const int row = u >> 4, ch = u & 15;
        const uint32_t d = (uint32_t)((row * 16 + (ch ^ (row & 7))) * 16);
        CP_ASYNC16(sQ + d, Qf + (size_t)(m0 + row) * D_EMB + n * HD + ch * 8);
    }
    CP_COMMIT();
    // group 2: K(0)
    for (int u = tid; u < 1024; u += 128) {
        const int row = u >> 4, ch = u & 15;
        const uint32_t d = (uint32_t)((row * 16 + (ch ^ (row & 7))) * 16);
        CP_ASYNC16(sK + d, Kf + (size_t)row * D_EMB + n * HD + ch * 8);
    }
    CP_COMMIT();
    // group 3: V(0)
    for (int u = tid; u < 1024; u += 128) {
        const int row = u >> 4, ch = u & 15;
        const uint32_t d = (uint32_t)((row * 16 + (ch ^ (row & 7))) * 16);
        CP_ASYNC16(sV + d, Vf + (size_t)row * D_EMB + n * HD + ch * 8);
    }
    CP_COMMIT();

    float acc[2][16][4];
#pragma unroll
    for (int mt = 0; mt < 2; mt++)
#pragma unroll
        for (int ht = 0; ht < 16; ht++)
#pragma unroll
            for (int e = 0; e < 4; e++) acc[mt][ht][e] = 0.0f;
    float M0[2] = {-1e30f, -1e30f}, M1[2] = {-1e30f, -1e30f};
    float L0[2] = {0.0f, 0.0f}, L1[2] = {0.0f, 0.0f};

    const int NT = T_SEQ / 64;
    for (int it = 0; it < NT; it++) {
        CP_WAIT(1);
        __syncthreads();

        // ---- S = Q K^T for 2 m-tiles (32 rows) ----
        float c[2][8][4];
#pragma unroll
        for (int mt = 0; mt < 2; mt++)
#pragma unroll
            for (int t = 0; t < 8; t++)
#pragma unroll
                for (int e = 0; e < 4; e++) c[mt][t][e] = 0.0f;

#pragma unroll
        for (int kk = 0; kk < 8; kk++) {
            uint32_t q4[2][4];
#pragma unroll
            for (int mt = 0; mt < 2; mt++) {
                const int row = w * 32 + mt * 16 + lr + (lg & 1) * 8;
                const int ch = kk * 2 + (lg >> 1);
                const uint32_t a = (uint32_t)((row * 16 + (ch ^ (row & 7))) * 16);
                ldsm_x4(q4[mt][0], q4[mt][1], q4[mt][2], q4[mt][3], sQ + a);
            }
#pragma unroll
            for (int np = 0; np < 4; np++) {
                uint32_t k4[4];
                const int row = np * 16 + lr + (lg >> 1) * 8;
                const int ch = kk * 2 + (lg & 1);
                const uint32_t a = (uint32_t)((row * 16 + (ch ^ (row & 7))) * 16);
                ldsm_x4(k4[0], k4[1], k4[2], k4[3], sK + a);
#pragma unroll
                for (int mt = 0; mt < 2; mt++) {
                    mma16816(c[mt][np * 2],     q4[mt], &k4[0]);
                    mma16816(c[mt][np * 2 + 1], q4[mt], &k4[2]);
                }
            }
        }
        __syncthreads();  // done reading K tile

        // prefetch K(it+1)
        if (it + 1 < NT) {
            for (int u = tid; u < 1024; u += 128) {
                const int row = u >> 4, ch = u & 15;
                const uint32_t d = (uint32_t)((row * 16 + (ch ^ (row & 7))) * 16);
                CP_ASYNC16(sK + d, Kf + (size_t)((it + 1) * 64 + row) * D_EMB +
                                       n * HD + ch * 8);
            }
            CP_COMMIT();
        }

        // ---- online softmax (per m-tile) ----
#pragma unroll
        for (int mt = 0; mt < 2; mt++) {
            float mx0 = -1e30f, mx1 = -1e30f;
#pragma unroll
            for (int t = 0; t < 8; t++) {
                mx0 = fmaxf(mx0, fmaxf(c[mt][t][0], c[mt][t][1]));
                mx1 = fmaxf(mx1, fmaxf(c[mt][t][2], c[mt][t][3]));
            }
            mx0 = fmaxf(mx0, __shfl_xor_sync(0xffffffffu, mx0, 1));
            mx0 = fmaxf(mx0, __shfl_xor_sync(0xffffffffu, mx0, 2));
            mx1 = fmaxf(mx1, __shfl_xor_sync(0xffffffffu, mx1, 1));
            mx1 = fmaxf(mx1, __shfl_xor_sync(0xffffffffu, mx1, 2));

            const float Mn0 = fmaxf(M0[mt], mx0), Mn1 = fmaxf(M1[mt], mx1);
            const float a0 = __expf(M0[mt] - Mn0), a1 = __expf(M1[mt] - Mn1);
            float sum0 = 0.0f, sum1 = 0.0f;
#pragma unroll
            for (int t = 0; t < 8; t++) {
                c[mt][t][0] = __expf(c[mt][t][0] - Mn0);
                c[mt][t][1] = __expf(c[mt][t][1] - Mn0);
                c[mt][t][2] = __expf(c[mt][t][2] - Mn1);
                c[mt][t][3] = __expf(c[mt][t][3] - Mn1);
                sum0 += c[mt][t][0] + c[mt][t][1];
                sum1 += c[mt][t][2] + c[mt][t][3];
            }
            sum0 += __shfl_xor_sync(0xffffffffu, sum0, 1);
            sum0 += __shfl_xor_sync(0xffffffffu, sum0, 2);
            sum1 += __shfl_xor_sync(0xffffffffu, sum1, 1);
            sum1 += __shfl_xor_sync(0xffffffffu, sum1, 2);
            L0[mt] = L0[mt] * a0 + sum0;
            L1[mt] = L1[mt] * a1 + sum1;
            M0[mt] = Mn0;
            M1[mt] = Mn1;
#pragma unroll
            for (int ht = 0; ht < 16; ht++) {
                acc[mt][ht][0] *= a0;
                acc[mt][ht][1] *= a0;
                acc[mt][ht][2] *= a1;
                acc[mt][ht][3] *= a1;
            }
        }

        // V(it) ready
        if (it + 1 < NT) {
            CP_WAIT(1);
        } else {
            CP_WAIT(0);
        }
        __syncthreads();

        // ---- O += P V (V fragment loaded once, used by both m-tiles) ----
#pragma unroll
        for (int kk = 0; kk < 4; kk++) {
            uint32_t ap[2][4];
#pragma unroll
            for (int mt = 0; mt < 2; mt++) {
                const int t0 = kk * 2, t1 = kk * 2 + 1;
                ap[mt][0] = pack_f16(c[mt][t0][0], c[mt][t0][1]);
                ap[mt][1] = pack_f16(c[mt][t0][2], c[mt][t0][3]);
                ap[mt][2] = pack_f16(c[mt][t1][0], c[mt][t1][1]);
                ap[mt][3] = pack_f16(c[mt][t1][2], c[mt][t1][3]);
            }
#pragma unroll
            for (int hq = 0; hq < 8; hq++) {
                uint32_t v4[4];
                const int row = kk * 16 + (lg & 1) * 8 + lr;
                const int ch = hq * 2 + (lg >> 1);
                const uint32_t a = (uint32_t)((row * 16 + (ch ^ (row & 7))) * 16);
                ldsm_x4_t(v4[0], v4[1], v4[2], v4[3], sV + a);
#pragma unroll
                for (int mt = 0; mt < 2; mt++) {
                    mma16816(acc[mt][hq * 2],     ap[mt], &v4[0]);
                    mma16816(acc[mt][hq * 2 + 1], ap[mt], &v4[2]);
                }
            }
        }
        __syncthreads();  // done reading V tile

        // prefetch V(it+1)
        if (it + 1 < NT) {
            for (int u = tid; u < 1024; u += 128) {
                const int row = u >> 4, ch = u & 15;
                const uint32_t d = (uint32_t)((row * 16 + (ch ^ (row & 7))) * 16);
                CP_ASYNC16(sV + d, Vf + (size_t)((it + 1) * 64 + row) * D_EMB +
                                       n * HD + ch * 8);
            }
            CP_COMMIT();
        }
    }

#pragma unroll
    for (int mt = 0; mt < 2; mt++) {
        const float i0 = 1.0f / L0[mt], i1 = 1.0f / L1[mt];
        const int rowg = m0 + w * 32 + mt * 16 + (lane >> 2);
#pragma unroll
        for (int ht = 0; ht < 16; ht++) {
            const int col = n * HD + ht * 8 + (lane & 3) * 2;
            *reinterpret_cast<uint32_t*>(&Rf[(size_t)rowg * D_EMB + col]) =
                pack_f16(acc[mt][ht][0] * i0, acc[mt][ht][1] * i0);
            *reinterpret_cast<uint32_t*>(&Rf[(size_t)(rowg + 8) * D_EMB + col]) =
                pack_f16(acc[mt][ht][2] * i1, acc[mt][ht][3] * i1);
        }
    }
}

// ---------------------------------------------------------------------------
extern "C" void kernel_launch(void* const* d_in, const int* in_sizes, int n_in,
                              void* d_out, int out_size) {
    const float* X  = (const float*)d_in[0];
    const float* Wq = (const float*)d_in[1];
    const float* Wk = (const float*)d_in[2];
    const float* Wv = (const float*)d_in[3];
    const float* Wo = (const float*)d_in[4];
    float* out = (float*)d_out;

    __half *xf, *rf, *qf, *kf, *vf;
    __half *wqh, *wql, *wkh, *wkl, *wvh, *wvl, *woh, *wol;
    cudaGetSymbolAddress((void**)&xf, g_Xf);
    cudaGetSymbolAddress((void**)&rf, g_Rf);
    cudaGetSymbolAddress((void**)&qf, g_Qf);
    cudaGetSymbolAddress((void**)&kf, g_Kf);
    cudaGetSymbolAddress((void**)&vf, g_Vf);
    cudaGetSymbolAddress((void**)&wqh, g_Wqh);
    cudaGetSymbolAddress((void**)&wql, g_Wql);
    cudaGetSymbolAddress((void**)&wkh, g_Wkh);
    cudaGetSymbolAddress((void**)&wkl, g_Wkl);
    cudaGetSymbolAddress((void**)&wvh, g_Wvh);
    cudaGetSymbolAddress((void**)&wvl, g_Wvl);
    cudaGetSymbolAddress((void**)&woh, g_Woh);
    cudaGetSymbolAddress((void**)&wol, g_Wol);

    const int NELE4 = T_SEQ * D_EMB / 4 / 256;

    // conversions (single merged weight kernel)
    convX<<<NELE4, 256>>>(X, xf);
    convW16all<<<dim3(64, 64, 4), dim3(32, 8)>>>(Wq, Wk, Wv, Wo, wqh, wql, wkh,
                                                 wkl, wvh, wvl, woh, wol);

    // fused QKV projection
    cudaFuncSetAttribute(gemm_qkv, cudaFuncAttributeMaxDynamicSharedMemorySize,
                         GEMM_SMEM);
    cudaFuncSetAttribute(gemm_out, cudaFuncAttributeMaxDynamicSharedMemorySize,
                         GEMM_SMEM);
    gemm_qkv<<<dim3(D_EMB / BN, T_SEQ / BM, 3), 128, GEMM_SMEM>>>(
        xf, wqh, wql, wkh, wkl, wvh, wvl, qf, kf, vf);

    // flash attention (128 rows/CTA)
    cudaFuncSetAttribute(attn_mma, cudaFuncAttributeMaxDynamicSharedMemorySize,
                         ATTN_SMEM);
    attn_mma<<<dim3(T_SEQ / 128, NHEADS), 128, ATTN_SMEM>>>(qf, kf, vf, rf);

    // out-projection
    gemm_out<<<dim3(D_EMB / BN, T_SEQ / BM), 128, GEMM_SMEM>>>(rf, woh, wol, out);
}

// round 9
// speedup vs baseline: 10.6860x; 1.5262x over previous
#include <cuda_runtime.h>
#include <cuda_fp16.h>
#include <stdint.h>
#include <math.h>

#define T_SEQ 2048
#define D_EMB 2048
#define HD    128
#define NHEADS 16
#define QK_SCALE 0.08838834764831843f
#define WSCALE 256.0f
#define INV_WSCALE (1.0f / 256.0f)

// ---------------- scratch (no allocs allowed) ----------------
__device__ __half g_Xf[T_SEQ * D_EMB];
__device__ __half g_Rf[T_SEQ * D_EMB];
// weights transposed [N=out][K=in], x256, single fp16
__device__ __half g_Wq[D_EMB * D_EMB];
__device__ __half g_Wk[D_EMB * D_EMB];
__device__ __half g_Wv[D_EMB * D_EMB];
__device__ __half g_Wo[D_EMB * D_EMB];
__device__ __half g_Qf[T_SEQ * D_EMB];
__device__ __half g_Kf[T_SEQ * D_EMB];
__device__ __half g_Vf[T_SEQ * D_EMB];

// ---------------- PTX helpers (base sm_103-legal only) ----------------
__device__ __forceinline__ uint32_t smem_u32(const void* p) {
    uint32_t a;
    asm("{ .reg .u64 t; cvta.to.shared.u64 t, %1; cvt.u32.u64 %0, t; }"
        : "=r"(a) : "l"(p));
    return a;
}
#define CP_ASYNC16(dst, src) \
    asm volatile("cp.async.cg.shared.global [%0], [%1], 16;" :: "r"(dst), "l"(src))
#define CP_COMMIT() asm volatile("cp.async.commit_group;" ::: "memory")
#define CP_WAIT(n) asm volatile("cp.async.wait_group %0;" :: "n"(n) : "memory")

__device__ __forceinline__ void ldsm_x4(uint32_t& r0, uint32_t& r1, uint32_t& r2,
                                        uint32_t& r3, uint32_t addr) {
    asm volatile("ldmatrix.sync.aligned.m8n8.x4.shared.b16 {%0,%1,%2,%3}, [%4];"
                 : "=r"(r0), "=r"(r1), "=r"(r2), "=r"(r3) : "r"(addr));
}
__device__ __forceinline__ void ldsm_x4_t(uint32_t& r0, uint32_t& r1, uint32_t& r2,
                                          uint32_t& r3, uint32_t addr) {
    asm volatile(
        "ldmatrix.sync.aligned.m8n8.x4.trans.shared.b16 {%0,%1,%2,%3}, [%4];"
        : "=r"(r0), "=r"(r1), "=r"(r2), "=r"(r3) : "r"(addr));
}
__device__ __forceinline__ void mma16816(float* c, const uint32_t* a,
                                         const uint32_t* b) {
    asm volatile(
        "mma.sync.aligned.m16n8k16.row.col.f32.f16.f16.f32 "
        "{%0,%1,%2,%3}, {%4,%5,%6,%7}, {%8,%9}, {%0,%1,%2,%3};"
        : "+f"(c[0]), "+f"(c[1]), "+f"(c[2]), "+f"(c[3])
        : "r"(a[0]), "r"(a[1]), "r"(a[2]), "r"(a[3]), "r"(b[0]), "r"(b[1]));
}
__device__ __forceinline__ uint32_t pack_f16(float x, float y) {
    __half2 h = __floats2half2_rn(x, y);
    return *reinterpret_cast<uint32_t*>(&h);
}

// ---------------- conversion kernels ----------------
__global__ __launch_bounds__(256) void convX(const float* __restrict__ A,
                                             __half* __restrict__ F) {
    const int i = blockIdx.x * 256 + threadIdx.x;
    float4 v = reinterpret_cast<const float4*>(A)[i];
    __half f[4] = {__float2half_rn(v.x), __float2half_rn(v.y),
                   __float2half_rn(v.z), __float2half_rn(v.w)};
    reinterpret_cast<uint2*>(F)[i] = *reinterpret_cast<uint2*>(f);
}

// merged weight conversion: z = 0/1/2 -> Wq/Wk/Wv (16 heads, hd=128);
// z = 3 -> Wo (hd=2048). Output transposed [N][K], x256, single fp16.
__global__ __launch_bounds__(256) void convW16all(
    const float* __restrict__ Wq, const float* __restrict__ Wk,
    const float* __restrict__ Wv, const float* __restrict__ Wo,
    __half* __restrict__ Hq, __half* __restrict__ Hk,
    __half* __restrict__ Hv, __half* __restrict__ Ho) {
    __shared__ float t[32][33];
    const int z = blockIdx.z;
    const float* W = (z == 0) ? Wq : (z == 1) ? Wk : (z == 2) ? Wv : Wo;
    __half* H = (z == 0) ? Hq : (z == 1) ? Hk : (z == 2) ? Hv : Ho;
    const int hd = (z == 3) ? D_EMB : HD;
    const int n  = (z == 3) ? 0 : (blockIdx.x >> 2);
    const int j0 = (z == 3) ? (blockIdx.x * 32) : ((blockIdx.x & 3) * 32);
    const int k0 = blockIdx.y * 32;
    const int tx = threadIdx.x, ty = threadIdx.y;
    const float* Wn = W + (size_t)n * D_EMB * hd;
#pragma unroll
    for (int y = ty; y < 32; y += 8) t[y][tx] = Wn[(size_t)(k0 + y) * hd + j0 + tx];
    __syncthreads();
#pragma unroll
    for (int y = ty; y < 32; y += 8) {
        H[(size_t)(n * hd + j0 + y) * D_EMB + k0 + tx] =
            __float2half_rn(t[tx][y] * WSCALE);
    }
}

// ---------------- 1-pass fp16 HMMA GEMM (warp 64x64, 128 threads) ----------------
#define BM 128
#define BN 128
#define BK 32
#define STAGE_B 16384
#define GEMM_SMEM (3 * STAGE_B)

__device__ __forceinline__ uint32_t swz(uint32_t base, int row, int chunk) {
    return base + (((row << 2) + (chunk ^ ((row >> 1) & 3))) << 4);
}

__device__ __forceinline__ void stage_tile(uint32_t sbase,
                                           const __half* __restrict__ g,
                                           int row0, int k0, int tid) {
#pragma unroll
    for (int u = tid; u < 512; u += 128) {
        const int row = u >> 2, ch = u & 3;
        const uint32_t dst = swz(sbase, row, ch);
        const __half* src = g + (size_t)(row0 + row) * D_EMB + k0 + ch * 8;
        CP_ASYNC16(dst, src);
    }
}

__device__ __forceinline__ void stage_all(uint32_t sbase, const __half* Af,
                                          const __half* Bf, int bm, int bn,
                                          int k0, int tid) {
    stage_tile(sbase + 0,    Af, bm, k0, tid);
    stage_tile(sbase + 8192, Bf, bn, k0, tid);
    CP_COMMIT();
}

__device__ __forceinline__ void gemm_core1(
    uint32_t sb, const __half* Af, const __half* Bf, int bm, int bn, int tid,
    float acc[4][8][4]) {
    const int lane = tid & 31;
    const int wid = tid >> 5;
    const int wm = wid & 1;   // 2x2 warp grid
    const int wn = wid >> 1;
    const int lr = lane & 7;
    const int lg = lane >> 3;

#pragma unroll
    for (int mt = 0; mt < 4; mt++)
#pragma unroll
        for (int nt = 0; nt < 8; nt++)
#pragma unroll
            for (int e = 0; e < 4; e++) acc[mt][nt][e] = 0.0f;

    stage_all(sb + 0 * STAGE_B, Af, Bf, bm, bn, 0, tid);
    stage_all(sb + 1 * STAGE_B, Af, Bf, bm, bn, BK, tid);

    const int NITER = D_EMB / BK;  // 64
    for (int c = 0; c < NITER; c++) {
        if (c == NITER - 1) {
            CP_WAIT(0);
        } else {
            CP_WAIT(1);
        }
        __syncthreads();
        if (c + 2 < NITER)
            stage_all(sb + ((c + 2) % 3) * STAGE_B, Af, Bf, bm, bn,
                      (c + 2) * BK, tid);

        const uint32_t sX = sb + (c % 3) * STAGE_B;
        const uint32_t sB = sX + 8192;

#pragma unroll
        for (int kk = 0; kk < 2; kk++) {
            uint32_t a4[4][4];
#pragma unroll
            for (int mt = 0; mt < 4; mt++) {
                const int row = wm * 64 + mt * 16 + lr + (lg & 1) * 8;
                const int ch = kk * 2 + (lg >> 1);
                ldsm_x4(a4[mt][0], a4[mt][1], a4[mt][2], a4[mt][3],
                        swz(sX, row, ch));
            }
            uint32_t b4[8][2];
#pragma unroll
            for (int np = 0; np < 4; np++) {
                const int row = wn * 64 + np * 16 + lr + (lg >> 1) * 8;
                const int ch = kk * 2 + (lg & 1);
                ldsm_x4(b4[np * 2][0], b4[np * 2][1], b4[np * 2 + 1][0],
                        b4[np * 2 + 1][1], swz(sB, row, ch));
            }
#pragma unroll
            for (int mt = 0; mt < 4; mt++)
#pragma unroll
                for (int nt = 0; nt < 8; nt++)
                    mma16816(acc[mt][nt], a4[mt], b4[nt]);
        }
    }
    __syncthreads();
}

// fused QKV: z=0 -> Q (scaled); z=1 -> K; z=2 -> V; all single fp16
__global__ __launch_bounds__(128, 2) void gemm_qkv(
    const __half* __restrict__ Xf, const __half* __restrict__ Wq,
    const __half* __restrict__ Wk, const __half* __restrict__ Wv,
    __half* __restrict__ Qf, __half* __restrict__ Kf, __half* __restrict__ Vf) {
    extern __shared__ char sm[];
    const uint32_t sb = smem_u32(sm);
    const int tid = threadIdx.x;
    const int lane = tid & 31;
    const int wid = tid >> 5;
    const int z = blockIdx.z;
    const int bm = blockIdx.y * BM;
    const int bn = blockIdx.x * BN;

    const __half* Bf = (z == 0) ? Wq : (z == 1) ? Wk : Wv;

    float acc[4][8][4];
    gemm_core1(sb, Xf, Bf, bm, bn, tid, acc);

    const int wm = wid & 1;
    const int wn = wid >> 1;
    __half* Dst = (z == 0) ? Qf : (z == 1) ? Kf : Vf;
    const float s = (z == 0) ? (QK_SCALE * INV_WSCALE) : INV_WSCALE;
#pragma unroll
    for (int mt = 0; mt < 4; mt++) {
        const int row = bm + wm * 64 + mt * 16 + (lane >> 2);
#pragma unroll
        for (int nt = 0; nt < 8; nt++) {
            const int col = bn + wn * 64 + nt * 8 + (lane & 3) * 2;
            *reinterpret_cast<uint32_t*>(&Dst[(size_t)row * D_EMB + col]) =
                pack_f16(acc[mt][nt][0] * s, acc[mt][nt][1] * s);
            *reinterpret_cast<uint32_t*>(&Dst[(size_t)(row + 8) * D_EMB + col]) =
                pack_f16(acc[mt][nt][2] * s, acc[mt][nt][3] * s);
        }
    }
}

// out-projection: fp32 output
__global__ __launch_bounds__(128, 2) void gemm_out(
    const __half* __restrict__ Af, const __half* __restrict__ Bf,
    float* __restrict__ C) {
    extern __shared__ char sm[];
    const uint32_t sb = smem_u32(sm);
    const int tid = threadIdx.x;
    const int lane = tid & 31;
    const int wid = tid >> 5;
    const int bm = blockIdx.y * BM;
    const int bn = blockIdx.x * BN;

    float acc[4][8][4];
    gemm_core1(sb, Af, Bf, bm, bn, tid, acc);

    const int wm = wid & 1;
    const int wn = wid >> 1;
#pragma unroll
    for (int mt = 0; mt < 4; mt++) {
        const int row = bm + wm * 64 + mt * 16 + (lane >> 2);
#pragma unroll
        for (int nt = 0; nt < 8; nt++) {
            const int col = bn + wn * 64 + nt * 8 + (lane & 3) * 2;
            *reinterpret_cast<float2*>(&C[(size_t)row * D_EMB + col]) =
                make_float2(acc[mt][nt][0] * INV_WSCALE, acc[mt][nt][1] * INV_WSCALE);
            *reinterpret_cast<float2*>(&C[(size_t)(row + 8) * D_EMB + col]) =
                make_float2(acc[mt][nt][2] * INV_WSCALE, acc[mt][nt][3] * INV_WSCALE);
        }
    }
}

// ---------------- fp16 HMMA flash attention (32 rows/warp) ----------------
#define ATTN_SMEM 65536

__global__ __launch_bounds__(128, 2) void attn_mma(
    const __half* __restrict__ Qf, const __half* __restrict__ Kf,
    const __half* __restrict__ Vf, __half* __restrict__ Rf) {
    extern __shared__ char sm[];
    const uint32_t sb = smem_u32(sm);
    const uint32_t sQ = sb;
    const uint32_t sK = sb + 32768;
    const uint32_t sV = sb + 49152;

    const int n = blockIdx.y;
    const int m0 = blockIdx.x * 128;
    const int tid = threadIdx.x;
    const int lane = tid & 31;
    const int w = tid >> 5;
    const int lr = lane & 7;
    const int lg = lane >> 3;

    // group 1: Q (128 rows x 256B)
    for (int u = tid; u < 2048; u += 128) {
        const int row = u >> 4, ch = u & 15;
        const uint32_t d = (uint32_t)((row * 16 + (ch ^ (row & 7))) * 16);
        CP_ASYNC16(sQ + d, Qf + (size_t)(m0 + row) * D_EMB + n * HD + ch * 8);
    }
    CP_COMMIT();
    // group 2: K(0)
    for (int u = tid; u < 1024; u += 128) {
        const int row = u >> 4, ch = u & 15;
        const uint32_t d = (uint32_t)((row * 16 + (ch ^ (row & 7))) * 16);
        CP_ASYNC16(sK + d, Kf + (size_t)row * D_EMB + n * HD + ch * 8);
    }
    CP_COMMIT();
    // group 3: V(0)
    for (int u = tid; u < 1024; u += 128) {
        const int row = u >> 4, ch = u & 15;
        const uint32_t d = (uint32_t)((row * 16 + (ch ^ (row & 7))) * 16);
        CP_ASYNC16(sV + d, Vf + (size_t)row * D_EMB + n * HD + ch * 8);
    }
    CP_COMMIT();

    float acc[2][16][4];
#pragma unroll
    for (int mt = 0; mt < 2; mt++)
#pragma unroll
        for (int ht = 0; ht < 16; ht++)
#pragma unroll
            for (int e = 0; e < 4; e++) acc[mt][ht][e] = 0.0f;
    float M0[2] = {-1e30f, -1e30f}, M1[2] = {-1e30f, -1e30f};
    float L0[2] = {0.0f, 0.0f}, L1[2] = {0.0f, 0.0f};

    const int NT = T_SEQ / 64;
    for (int it = 0; it < NT; it++) {
        CP_WAIT(1);
        __syncthreads();

        // ---- S = Q K^T for 2 m-tiles ----
        float c[2][8][4];
#pragma unroll
        for (int mt = 0; mt < 2; mt++)
#pragma unroll
            for (int t = 0; t < 8; t++)
#pragma unroll
                for (int e = 0; e < 4; e++) c[mt][t][e] = 0.0f;

#pragma unroll
        for (int kk = 0; kk < 8; kk++) {
            uint32_t q4[2][4];
#pragma unroll
            for (int mt = 0; mt < 2; mt++) {
                const int row = w * 32 + mt * 16 + lr + (lg & 1) * 8;
                const int ch = kk * 2 + (lg >> 1);
                const uint32_t a = (uint32_t)((row * 16 + (ch ^ (row & 7))) * 16);
                ldsm_x4(q4[mt][0], q4[mt][1], q4[mt][2], q4[mt][3], sQ + a);
            }
#pragma unroll
            for (int np = 0; np < 4; np++) {
                uint32_t k4[4];
                const int row = np * 16 + lr + (lg >> 1) * 8;
                const int ch = kk * 2 + (lg & 1);
                const uint32_t a = (uint32_t)((row * 16 + (ch ^ (row & 7))) * 16);
                ldsm_x4(k4[0], k4[1], k4[2], k4[3], sK + a);
#pragma unroll
                for (int mt = 0; mt < 2; mt++) {
                    mma16816(c[mt][np * 2],     q4[mt], &k4[0]);
                    mma16816(c[mt][np * 2 + 1], q4[mt], &k4[2]);
                }
            }
        }
        __syncthreads();

        // prefetch K(it+1)
        if (it + 1 < NT) {
            for (int u = tid; u < 1024; u += 128) {
                const int row = u >> 4, ch = u & 15;
                const uint32_t d = (uint32_t)((row * 16 + (ch ^ (row & 7))) * 16);
                CP_ASYNC16(sK + d, Kf + (size_t)((it + 1) * 64 + row) * D_EMB +
                                       n * HD + ch * 8);
            }
            CP_COMMIT();
        }

        // ---- online softmax ----
#pragma unroll
        for (int mt = 0; mt < 2; mt++) {
            float mx0 = -1e30f, mx1 = -1e30f;
#pragma unroll
            for (int t = 0; t < 8; t++) {
                mx0 = fmaxf(mx0, fmaxf(c[mt][t][0], c[mt][t][1]));
                mx1 = fmaxf(mx1, fmaxf(c[mt][t][2], c[mt][t][3]));
            }
            mx0 = fmaxf(mx0, __shfl_xor_sync(0xffffffffu, mx0, 1));
            mx0 = fmaxf(mx0, __shfl_xor_sync(0xffffffffu, mx0, 2));
            mx1 = fmaxf(mx1, __shfl_xor_sync(0xffffffffu, mx1, 1));
            mx1 = fmaxf(mx1, __shfl_xor_sync(0xffffffffu, mx1, 2));

            const float Mn0 = fmaxf(M0[mt], mx0), Mn1 = fmaxf(M1[mt], mx1);
            const float a0 = __expf(M0[mt] - Mn0), a1 = __expf(M1[mt] - Mn1);
            float sum0 = 0.0f, sum1 = 0.0f;
#pragma unroll
            for (int t = 0; t < 8; t++) {
                c[mt][t][0] = __expf(c[mt][t][0] - Mn0);
                c[mt][t][1] = __expf(c[mt][t][1] - Mn0);
                c[mt][t][2] = __expf(c[mt][t][2] - Mn1);
                c[mt][t][3] = __expf(c[mt][t][3] - Mn1);
                sum0 += c[mt][t][0] + c[mt][t][1];
                sum1 += c[mt][t][2] + c[mt][t][3];
            }
            sum0 += __shfl_xor_sync(0xffffffffu, sum0, 1);
            sum0 += __shfl_xor_sync(0xffffffffu, sum0, 2);
            sum1 += __shfl_xor_sync(0xffffffffu, sum1, 1);
            sum1 += __shfl_xor_sync(0xffffffffu, sum1, 2);
            L0[mt] = L0[mt] * a0 + sum0;
            L1[mt] = L1[mt] * a1 + sum1;
            M0[mt] = Mn0;
            M1[mt] = Mn1;
#pragma unroll
            for (int ht = 0; ht < 16; ht++) {
                acc[mt][ht][0] *= a0;
                acc[mt][ht][1] *= a0;
                acc[mt][ht][2] *= a1;
                acc[mt][ht][3] *= a1;
            }
        }

        // V(it) ready
        if (it + 1 < NT) {
            CP_WAIT(1);
        } else {
            CP_WAIT(0);
        }
        __syncthreads();

        // ---- O += P V ----
#pragma unroll
        for (int kk = 0; kk < 4; kk++) {
            uint32_t ap[2][4];
#pragma unroll
            for (int mt = 0; mt < 2; mt++) {
                const int t0 = kk * 2, t1 = kk * 2 + 1;
                ap[mt][0] = pack_f16(c[mt][t0][0], c[mt][t0][1]);
                ap[mt][1] = pack_f16(c[mt][t0][2], c[mt][t0][3]);
                ap[mt][2] = pack_f16(c[mt][t1][0], c[mt][t1][1]);
                ap[mt][3] = pack_f16(c[mt][t1][2], c[mt][t1][3]);
            }
#pragma unroll
            for (int hq = 0; hq < 8; hq++) {
                uint32_t v4[4];
                const int row = kk * 16 + (lg & 1) * 8 + lr;
                const int ch = hq * 2 + (lg >> 1);
                const uint32_t a = (uint32_t)((row * 16 + (ch ^ (row & 7))) * 16);
                ldsm_x4_t(v4[0], v4[1], v4[2], v4[3], sV + a);
#pragma unroll
                for (int mt = 0; mt < 2; mt++) {
                    mma16816(acc[mt][hq * 2],     ap[mt], &v4[0]);
                    mma16816(acc[mt][hq * 2 + 1], ap[mt], &v4[2]);
                }
            }
        }
        __syncthreads();

        // prefetch V(it+1)
        if (it + 1 < NT) {
            for (int u = tid; u < 1024; u += 128) {
                const int row = u >> 4, ch = u & 15;
                const uint32_t d = (uint32_t)((row * 16 + (ch ^ (row & 7))) * 16);
                CP_ASYNC16(sV + d, Vf + (size_t)((it + 1) * 64 + row) * D_EMB +
                                       n * HD + ch * 8);
            }
            CP_COMMIT();
        }
    }

#pragma unroll
    for (int mt = 0; mt < 2; mt++) {
        const float i0 = 1.0f / L0[mt], i1 = 1.0f / L1[mt];
        const int rowg = m0 + w * 32 + mt * 16 + (lane >> 2);
#pragma unroll
        for (int ht = 0; ht < 16; ht++) {
            const int col = n * HD + ht * 8 + (lane & 3) * 2;
            *reinterpret_cast<uint32_t*>(&Rf[(size_t)rowg * D_EMB + col]) =
                pack_f16(acc[mt][ht][0] * i0, acc[mt][ht][1] * i0);
            *reinterpret_cast<uint32_t*>(&Rf[(size_t)(rowg + 8) * D_EMB + col]) =
                pack_f16(acc[mt][ht][2] * i1, acc[mt][ht][3] * i1);
        }
    }
}

// ---------------------------------------------------------------------------
extern "C" void kernel_launch(void* const* d_in, const int* in_sizes, int n_in,
                              void* d_out, int out_size) {
    const float* X  = (const float*)d_in[0];
    const float* Wq = (const float*)d_in[1];
    const float* Wk = (const float*)d_in[2];
    const float* Wv = (const float*)d_in[3];
    const float* Wo = (const float*)d_in[4];
    float* out = (float*)d_out;

    __half *xf, *rf, *qf, *kf, *vf, *wq, *wk, *wv, *wo;
    cudaGetSymbolAddress((void**)&xf, g_Xf);
    cudaGetSymbolAddress((void**)&rf, g_Rf);
    cudaGetSymbolAddress((void**)&qf, g_Qf);
    cudaGetSymbolAddress((void**)&kf, g_Kf);
    cudaGetSymbolAddress((void**)&vf, g_Vf);
    cudaGetSymbolAddress((void**)&wq, g_Wq);
    cudaGetSymbolAddress((void**)&wk, g_Wk);
    cudaGetSymbolAddress((void**)&wv, g_Wv);
    cudaGetSymbolAddress((void**)&wo, g_Wo);

    const int NELE4 = T_SEQ * D_EMB / 4 / 256;

    // conversions
    convX<<<NELE4, 256>>>(X, xf);
    convW16all<<<dim3(64, 64, 4), dim3(32, 8)>>>(Wq, Wk, Wv, Wo, wq, wk, wv, wo);

    // fused QKV projection (1-pass fp16)
    cudaFuncSetAttribute(gemm_qkv, cudaFuncAttributeMaxDynamicSharedMemorySize,
                         GEMM_SMEM);
    cudaFuncSetAttribute(gemm_out, cudaFuncAttributeMaxDynamicSharedMemorySize,
                         GEMM_SMEM);
    gemm_qkv<<<dim3(D_EMB / BN, T_SEQ / BM, 3), 128, GEMM_SMEM>>>(xf, wq, wk, wv,
                                                                  qf, kf, vf);

    // flash attention
    cudaFuncSetAttribute(attn_mma, cudaFuncAttributeMaxDynamicSharedMemorySize,
                         ATTN_SMEM);
    attn_mma<<<dim3(T_SEQ / 128, NHEADS), 128, ATTN_SMEM>>>(qf, kf, vf, rf);

    // out-projection (1-pass fp16)
    gemm_out<<<dim3(D_EMB / BN, T_SEQ / BM), 128, GEMM_SMEM>>>(rf, wo, out);
}